// round 4
// baseline (speedup 1.0000x reference)
#include <cuda_runtime.h>
#include <cuda_bf16.h>
#include <cstdint>

// Problem constants
#define BB   32
#define MAXN 1024
#define FF   215
#define HH   256
#define TT   8
#define LL   3
#define NN   (BB * MAXN)        // 32768
#define EE   524288
#define H3   (3 * HH)           // 768
#define KS   2112               // s row stride: 2048 msg + 8 cnt + 56 pad (mult of 64)

// ---------------------------------------------------------------------------
// Scratch (static __device__ globals — allocation-free per harness rules)
// ---------------------------------------------------------------------------
__device__ __align__(128) float g_h [ (size_t)NN * HH ];
__device__ __align__(128) float g_s [ (size_t)NN * KS ];   // 277 MB
__device__ __align__(128) float g_m [ (size_t)NN * HH ];
__device__ __align__(128) float g_gi[ (size_t)NN * H3 ];
__device__ __align__(128) float g_gh[ (size_t)NN * H3 ];
__device__ __align__(128) float g_Wb[ (size_t)LL * HH * KS ];
// bf16 hi/lo split weights
__device__ __align__(128) __nv_bfloat16 g_Wbh [ (size_t)LL * HH * KS ];
__device__ __align__(128) __nv_bfloat16 g_Wbl [ (size_t)LL * HH * KS ];
__device__ __align__(128) __nv_bfloat16 g_Wph [ 256 * 256 ];
__device__ __align__(128) __nv_bfloat16 g_Wpl [ 256 * 256 ];
__device__ __align__(128) __nv_bfloat16 g_Wihh[ (size_t)LL * H3 * HH ];
__device__ __align__(128) __nv_bfloat16 g_Wihl[ (size_t)LL * H3 * HH ];
__device__ __align__(128) __nv_bfloat16 g_Whhh[ (size_t)LL * H3 * HH ];
__device__ __align__(128) __nv_bfloat16 g_Whhl[ (size_t)LL * H3 * HH ];

// ---------------------------------------------------------------------------
// Helpers (base PTX only — no sm_103a-gated features)
// ---------------------------------------------------------------------------
__device__ __forceinline__ uint32_t smem_u32(const void* p) {
    uint32_t a;
    asm("{ .reg .u64 t; cvta.to.shared.u64 t, %1; cvt.u32.u64 %0, t; }" : "=r"(a) : "l"(p));
    return a;
}

__device__ __forceinline__ void ldsm4(uint32_t& r0, uint32_t& r1, uint32_t& r2, uint32_t& r3,
                                      uint32_t addr)
{
    asm volatile("ldmatrix.sync.aligned.m8n8.x4.shared.b16 {%0,%1,%2,%3}, [%4];"
                 : "=r"(r0), "=r"(r1), "=r"(r2), "=r"(r3) : "r"(addr));
}

__device__ __forceinline__ void mma_bf16(float* c, const uint32_t* a, uint32_t b0, uint32_t b1)
{
    asm volatile("mma.sync.aligned.m16n8k16.row.col.f32.bf16.bf16.f32 "
                 "{%0,%1,%2,%3}, {%4,%5,%6,%7}, {%8,%9}, {%0,%1,%2,%3};"
                 : "+f"(c[0]), "+f"(c[1]), "+f"(c[2]), "+f"(c[3])
                 : "r"(a[0]), "r"(a[1]), "r"(a[2]), "r"(a[3]), "r"(b0), "r"(b1));
}

// split fp32 pair -> packed bf16x2 hi + bf16x2 lo  (lo = x - bf16(x))
__device__ __forceinline__ void split2(float x0, float x1, uint32_t& h01, uint32_t& l01) {
    asm("cvt.rn.bf16x2.f32 %0, %1, %2;" : "=r"(h01) : "f"(x1), "f"(x0));   // lo-half = x0
    float h0 = __uint_as_float(h01 << 16);
    float h1 = __uint_as_float(h01 & 0xFFFF0000u);
    float l0 = x0 - h0;
    float l1 = x1 - h1;
    asm("cvt.rn.bf16x2.f32 %0, %1, %2;" : "=r"(l01) : "f"(l1), "f"(l0));
}

// ---------------------------------------------------------------------------
// mma_gemm: C[M x Nc] = A[M x K] @ B[Nc x K]^T (+ bias), fp32 via bf16 3-MMA split.
// Block tile 128x128, K-chunk 32. 8 warps (2m x 4n), warp tile 64x32.
// A fp32 -> inline hi/lo split. B pre-split bf16 hi/lo in gmem.
// grid = (Nc/128, M/128), 256 threads.
// ---------------------------------------------------------------------------
#define SA 40   // smem row stride in bf16 elements (80B) -> conflict-free ldmatrix

__global__ void __launch_bounds__(256)
mma_gemm(const float* __restrict__ A, int lda, int Ka, int avec,
         const __nv_bfloat16* __restrict__ Bh, const __nv_bfloat16* __restrict__ Bl, int ldb,
         const float* __restrict__ bias, float* __restrict__ C, int ldc, int nch)
{
    __shared__ __align__(16) __nv_bfloat16 sAh[128 * SA];
    __shared__ __align__(16) __nv_bfloat16 sAl[128 * SA];
    __shared__ __align__(16) __nv_bfloat16 sBh[128 * SA];
    __shared__ __align__(16) __nv_bfloat16 sBl[128 * SA];

    const int tid  = threadIdx.x;
    const int wid  = tid >> 5;
    const int lane = tid & 31;
    const int m0   = blockIdx.y * 128;
    const int n0   = blockIdx.x * 128;
    const int wm0  = (wid >> 2) * 64;   // warp m-origin in block
    const int wn0  = (wid & 3) * 32;    // warp n-origin in block

    float acc[4][4][4];
#pragma unroll
    for (int i = 0; i < 4; i++)
#pragma unroll
        for (int j = 0; j < 4; j++)
#pragma unroll
            for (int f = 0; f < 4; f++) acc[i][j][f] = 0.0f;

    // ldmatrix per-lane geometry
    const int g  = lane >> 3;
    const int ri = lane & 7;
    const int aRow = ri + ((g & 1) ? 8 : 0);
    const int aK   = (g & 2) ? 8 : 0;
    const int bRow = ri + ((g & 2) ? 8 : 0);
    const int bK   = (g & 1) ? 8 : 0;

    const uint32_t bAh = smem_u32(sAh), bAl = smem_u32(sAl);
    const uint32_t bBh = smem_u32(sBh), bBl = smem_u32(sBl);
    const uint32_t aOff = (uint32_t)(((wm0 + aRow) * SA + aK) * 2);
    const uint32_t bOff = (uint32_t)(((wn0 + bRow) * SA + bK) * 2);

    // gmem staging registers
    float a_ld[16];
    uint4 bh_ld[2], bl_ld[2];

    // ---- prefetch chunk 0
    {
        const int k0 = 0;
#pragma unroll
        for (int s = 0; s < 4; ++s) {
            int idx = s * 256 + tid;
            int r = idx >> 3, cc = (idx & 7) * 4;
            const float* ap = A + (size_t)(m0 + r) * lda + (k0 + cc);
            if (avec) {
                float4 v = *(const float4*)ap;
                a_ld[s*4+0] = v.x; a_ld[s*4+1] = v.y; a_ld[s*4+2] = v.z; a_ld[s*4+3] = v.w;
            } else {
                int kg = k0 + cc;
                a_ld[s*4+0] = (kg   < Ka) ? ap[0] : 0.0f;
                a_ld[s*4+1] = (kg+1 < Ka) ? ap[1] : 0.0f;
                a_ld[s*4+2] = (kg+2 < Ka) ? ap[2] : 0.0f;
                a_ld[s*4+3] = (kg+3 < Ka) ? ap[3] : 0.0f;
            }
        }
#pragma unroll
        for (int s = 0; s < 2; ++s) {
            int idx = s * 256 + tid;
            int r = idx >> 2, cc = (idx & 3) * 8;
            size_t go = (size_t)(n0 + r) * ldb + (k0 + cc);
            bh_ld[s] = *(const uint4*)(Bh + go);
            bl_ld[s] = *(const uint4*)(Bl + go);
        }
    }

    for (int c = 0; c < nch; ++c) {
        __syncthreads();
        // ---- store staged chunk into smem (A split inline)
#pragma unroll
        for (int s = 0; s < 4; ++s) {
            int idx = s * 256 + tid;
            int r = idx >> 3, cc = (idx & 7) * 4;
            uint32_t h01, l01, h23, l23;
            split2(a_ld[s*4+0], a_ld[s*4+1], h01, l01);
            split2(a_ld[s*4+2], a_ld[s*4+3], h23, l23);
            uint32_t off = (uint32_t)((r * SA + cc) * 2);
            asm volatile("st.shared.v2.b32 [%0], {%1,%2};" :: "r"(bAh + off), "r"(h01), "r"(h23) : "memory");
            asm volatile("st.shared.v2.b32 [%0], {%1,%2};" :: "r"(bAl + off), "r"(l01), "r"(l23) : "memory");
        }
#pragma unroll
        for (int s = 0; s < 2; ++s) {
            int idx = s * 256 + tid;
            int r = idx >> 2, cc = (idx & 3) * 8;
            uint32_t off = (uint32_t)((r * SA + cc) * 2);
            uint4 vh = bh_ld[s], vl = bl_ld[s];
            asm volatile("st.shared.v4.b32 [%0], {%1,%2,%3,%4};"
                         :: "r"(bBh + off), "r"(vh.x), "r"(vh.y), "r"(vh.z), "r"(vh.w) : "memory");
            asm volatile("st.shared.v4.b32 [%0], {%1,%2,%3,%4};"
                         :: "r"(bBl + off), "r"(vl.x), "r"(vl.y), "r"(vl.z), "r"(vl.w) : "memory");
        }
        __syncthreads();

        // ---- prefetch next chunk (overlaps with MMA below)
        if (c + 1 < nch) {
            const int k0 = (c + 1) * 32;
#pragma unroll
            for (int s = 0; s < 4; ++s) {
                int idx = s * 256 + tid;
                int r = idx >> 3, cc = (idx & 7) * 4;
                const float* ap = A + (size_t)(m0 + r) * lda + (k0 + cc);
                if (avec) {
                    float4 v = *(const float4*)ap;
                    a_ld[s*4+0] = v.x; a_ld[s*4+1] = v.y; a_ld[s*4+2] = v.z; a_ld[s*4+3] = v.w;
                } else {
                    int kg = k0 + cc;
                    a_ld[s*4+0] = (kg   < Ka) ? ap[0] : 0.0f;
                    a_ld[s*4+1] = (kg+1 < Ka) ? ap[1] : 0.0f;
                    a_ld[s*4+2] = (kg+2 < Ka) ? ap[2] : 0.0f;
                    a_ld[s*4+3] = (kg+3 < Ka) ? ap[3] : 0.0f;
                }
            }
#pragma unroll
            for (int s = 0; s < 2; ++s) {
                int idx = s * 256 + tid;
                int r = idx >> 2, cc = (idx & 3) * 8;
                size_t go = (size_t)(n0 + r) * ldb + (k0 + cc);
                bh_ld[s] = *(const uint4*)(Bh + go);
                bl_ld[s] = *(const uint4*)(Bl + go);
            }
        }

        // ---- compute: two k16 sub-steps, 3 split products each
#pragma unroll
        for (int kh = 0; kh < 32; kh += 16) {
            uint32_t Af[4][4], Bf[2][4];
            // A-hi fragments
#pragma unroll
            for (int i = 0; i < 4; ++i)
                ldsm4(Af[i][0], Af[i][1], Af[i][2], Af[i][3],
                      bAh + aOff + (uint32_t)((i * 16 * SA + kh) * 2));
            // B-lo fragments
#pragma unroll
            for (int j = 0; j < 2; ++j)
                ldsm4(Bf[j][0], Bf[j][1], Bf[j][2], Bf[j][3],
                      bBl + bOff + (uint32_t)((j * 16 * SA + kh) * 2));
            // Ah * Bl
#pragma unroll
            for (int i = 0; i < 4; ++i)
#pragma unroll
                for (int jj = 0; jj < 4; ++jj)
                    mma_bf16(acc[i][jj], Af[i], Bf[jj>>1][(jj&1)*2], Bf[jj>>1][(jj&1)*2+1]);
            // B-hi fragments (overwrite Bf)
#pragma unroll
            for (int j = 0; j < 2; ++j)
                ldsm4(Bf[j][0], Bf[j][1], Bf[j][2], Bf[j][3],
                      bBh + bOff + (uint32_t)((j * 16 * SA + kh) * 2));
            // Ah * Bh
#pragma unroll
            for (int i = 0; i < 4; ++i)
#pragma unroll
                for (int jj = 0; jj < 4; ++jj)
                    mma_bf16(acc[i][jj], Af[i], Bf[jj>>1][(jj&1)*2], Bf[jj>>1][(jj&1)*2+1]);
            // A-lo fragments (overwrite Af)
#pragma unroll
            for (int i = 0; i < 4; ++i)
                ldsm4(Af[i][0], Af[i][1], Af[i][2], Af[i][3],
                      bAl + aOff + (uint32_t)((i * 16 * SA + kh) * 2));
            // Al * Bh
#pragma unroll
            for (int i = 0; i < 4; ++i)
#pragma unroll
                for (int jj = 0; jj < 4; ++jj)
                    mma_bf16(acc[i][jj], Af[i], Bf[jj>>1][(jj&1)*2], Bf[jj>>1][(jj&1)*2+1]);
        }
    }

    // ---- epilogue: direct gmem store with optional bias
    const int qr = lane >> 2;          // row within 8
    const int qc = (lane & 3) * 2;     // col within 8
#pragma unroll
    for (int i = 0; i < 4; ++i) {
        int row = m0 + wm0 + i * 16 + qr;
#pragma unroll
        for (int jj = 0; jj < 4; ++jj) {
            int col = n0 + wn0 + jj * 8 + qc;
            float b0 = 0.0f, b1 = 0.0f;
            if (bias) { b0 = bias[col]; b1 = bias[col + 1]; }
            float2 v0 = make_float2(acc[i][jj][0] + b0, acc[i][jj][1] + b1);
            float2 v1 = make_float2(acc[i][jj][2] + b0, acc[i][jj][3] + b1);
            *(float2*)(C + (size_t)row * ldc + col)       = v0;
            *(float2*)(C + (size_t)(row + 8) * ldc + col) = v1;
        }
    }
}

// ---------------------------------------------------------------------------
// Weight prep
// ---------------------------------------------------------------------------
__global__ void prep_wb_kernel(const float* __restrict__ Wm, const float* __restrict__ bm)
{
    int idx = blockIdx.x * blockDim.x + threadIdx.x;
    if (idx >= LL * HH * KS) return;
    int l   = idx / (HH * KS);
    int rem = idx % (HH * KS);
    int e   = rem / KS;
    int k   = rem % KS;
    float v = 0.0f;
    if (k < TT * HH) {
        int t = k >> 8, d = k & 255;
        v = Wm[((((size_t)l * TT + t) * HH) + e) * HH + d];
    } else if (k < TT * HH + TT) {
        int t = k - TT * HH;
        v = bm[((size_t)l * TT + t) * HH + e];
    }
    g_Wb[idx] = v;
}

__global__ void prep_split(const float* __restrict__ src,
                           __nv_bfloat16* __restrict__ hi, __nv_bfloat16* __restrict__ lo,
                           int rows, int K, int Kb)
{
    int idx = blockIdx.x * blockDim.x + threadIdx.x;
    if (idx >= rows * Kb) return;
    int r = idx / Kb, k = idx - r * Kb;
    float x = (k < K) ? src[(size_t)r * K + k] : 0.0f;
    __nv_bfloat16 hb = __float2bfloat16(x);
    hi[idx] = hb;
    lo[idx] = __float2bfloat16(x - __bfloat162float(hb));
}

// ---------------------------------------------------------------------------
// Scatter: one warp per edge. s[dst, type] += h[src]; cnt[dst, type] += 1
// ---------------------------------------------------------------------------
__device__ __forceinline__ void red_add_v4(float* p, float4 v)
{
    asm volatile("red.global.add.v4.f32 [%0], {%1, %2, %3, %4};"
                 :: "l"(p), "f"(v.x), "f"(v.y), "f"(v.z), "f"(v.w) : "memory");
}

__global__ void scatter_kernel(const int* __restrict__ edge_index,
                               const int* __restrict__ edge_type)
{
    int gw   = (blockIdx.x * blockDim.x + threadIdx.x) >> 5;
    int lane = threadIdx.x & 31;
    if (gw >= EE) return;
    int src = edge_index[gw];
    int dst = edge_index[EE + gw];
    int t   = edge_type[gw];

    const float4* hp = (const float4*)(g_h + (size_t)src * HH);
    float* sp = g_s + (size_t)dst * KS + t * HH;

    float4 v0 = hp[lane];
    float4 v1 = hp[lane + 32];
    red_add_v4(sp + lane * 4, v0);
    red_add_v4(sp + 128 + lane * 4, v1);
    if (lane == 0)
        atomicAdd(g_s + (size_t)dst * KS + TT * HH + t, 1.0f);
}

// ---------------------------------------------------------------------------
// GRU gate elementwise
// ---------------------------------------------------------------------------
__device__ __forceinline__ float sigmoidf_(float x) { return 1.0f / (1.0f + expf(-x)); }

__global__ void gru_kernel()
{
    int idx = blockIdx.x * blockDim.x + threadIdx.x;
    if (idx >= NN * HH) return;
    int n = idx >> 8;
    int j = idx & 255;
    const float* gi = g_gi + (size_t)n * H3;
    const float* gh = g_gh + (size_t)n * H3;
    float r  = sigmoidf_(gi[j]        + gh[j]);
    float z  = sigmoidf_(gi[HH + j]   + gh[HH + j]);
    float ng = tanhf   (gi[2*HH + j] + r * gh[2*HH + j]);
    float hv = g_h[idx];
    g_h[idx] = (1.0f - z) * ng + z * hv;
}

// ---------------------------------------------------------------------------
// Readout
// ---------------------------------------------------------------------------
__global__ void readout_kernel(float* __restrict__ out)
{
    int b = blockIdx.x;
    int c = blockIdx.y;
    int j = threadIdx.x;
    const float* hp = g_h + ((size_t)b * MAXN + (size_t)c * 128) * HH + j;
    float sum = 0.0f;
#pragma unroll 8
    for (int n = 0; n < 128; n++) sum += hp[(size_t)n * HH];
    atomicAdd(&out[b * HH + j], sum);
}

// ---------------------------------------------------------------------------
// Launch
// ---------------------------------------------------------------------------
extern "C" void kernel_launch(void* const* d_in, const int* in_sizes, int n_in,
                              void* d_out, int out_size)
{
    const float* node_features = (const float*)d_in[0];
    const int*   edge_index    = (const int*)  d_in[1];
    const int*   edge_type     = (const int*)  d_in[2];
    const float* Wp  = (const float*)d_in[3];
    const float* bp  = (const float*)d_in[4];
    const float* Wm  = (const float*)d_in[5];
    const float* bm  = (const float*)d_in[6];
    const float* Wih = (const float*)d_in[7];
    const float* Whh = (const float*)d_in[8];
    const float* bih = (const float*)d_in[9];
    const float* bhh = (const float*)d_in[10];
    float* out = (float*)d_out;

    float *p_h, *p_s, *p_m, *p_gi, *p_gh, *p_Wb;
    __nv_bfloat16 *p_Wbh, *p_Wbl, *p_Wph, *p_Wpl, *p_Wihh, *p_Wihl, *p_Whhh, *p_Whhl;
    cudaGetSymbolAddress((void**)&p_h,   g_h);
    cudaGetSymbolAddress((void**)&p_s,   g_s);
    cudaGetSymbolAddress((void**)&p_m,   g_m);
    cudaGetSymbolAddress((void**)&p_gi,  g_gi);
    cudaGetSymbolAddress((void**)&p_gh,  g_gh);
    cudaGetSymbolAddress((void**)&p_Wb,  g_Wb);
    cudaGetSymbolAddress((void**)&p_Wbh, g_Wbh);
    cudaGetSymbolAddress((void**)&p_Wbl, g_Wbl);
    cudaGetSymbolAddress((void**)&p_Wph, g_Wph);
    cudaGetSymbolAddress((void**)&p_Wpl, g_Wpl);
    cudaGetSymbolAddress((void**)&p_Wihh, g_Wihh);
    cudaGetSymbolAddress((void**)&p_Wihl, g_Wihl);
    cudaGetSymbolAddress((void**)&p_Whhh, g_Whhh);
    cudaGetSymbolAddress((void**)&p_Whhl, g_Whhl);

    // 0) weight prep: fold + split
    {
        int total = LL * HH * KS;
        prep_wb_kernel<<<(total + 255) / 256, 256>>>(Wm, bm);
        prep_split<<<(total + 255) / 256, 256>>>(p_Wb, p_Wbh, p_Wbl, LL * HH, KS, KS);
        int tp = 256 * 256;
        prep_split<<<(tp + 255) / 256, 256>>>(Wp, p_Wph, p_Wpl, HH, FF, 256);
        int tg = LL * H3 * HH;
        prep_split<<<(tg + 255) / 256, 256>>>(Wih, p_Wihh, p_Wihl, LL * H3, HH, HH);
        prep_split<<<(tg + 255) / 256, 256>>>(Whh, p_Whhh, p_Whhl, LL * H3, HH, HH);
    }

    // 1) input projection: h = X @ Wp^T + bp  (K=215 -> 7 chunks of 32, guarded)
    {
        dim3 grid(HH / 128, NN / 128);
        mma_gemm<<<grid, 256>>>(node_features, FF, FF, 0,
                                p_Wph, p_Wpl, 256, bp, p_h, HH, 7);
    }

    // 2) layers
    for (int l = 0; l < LL; l++) {
        cudaMemsetAsync(p_s, 0, (size_t)NN * KS * sizeof(float));

        scatter_kernel<<<(EE * 32) / 256, 256>>>(edge_index, edge_type);

        // m = s @ Wb[l]^T  (K = 2112 folds type-linears + cnt*bm bias)
        {
            dim3 grid(HH / 128, NN / 128);
            mma_gemm<<<grid, 256>>>(p_s, KS, KS, 1,
                                    p_Wbh + (size_t)l * HH * KS,
                                    p_Wbl + (size_t)l * HH * KS, KS,
                                    (const float*)0, p_m, HH, KS / 32);
        }
        // gi = m @ Wih[l]^T + bih[l]
        {
            dim3 grid(H3 / 128, NN / 128);
            mma_gemm<<<grid, 256>>>(p_m, HH, HH, 1,
                                    p_Wihh + (size_t)l * H3 * HH,
                                    p_Wihl + (size_t)l * H3 * HH, HH,
                                    bih + (size_t)l * H3, p_gi, H3, 8);
        }
        // gh = h @ Whh[l]^T + bhh[l]
        {
            dim3 grid(H3 / 128, NN / 128);
            mma_gemm<<<grid, 256>>>(p_h, HH, HH, 1,
                                    p_Whhh + (size_t)l * H3 * HH,
                                    p_Whhl + (size_t)l * H3 * HH, HH,
                                    bhh + (size_t)l * H3, p_gh, H3, 8);
        }
        gru_kernel<<<(NN * HH) / 256, 256>>>();
    }

    // 3) readout
    cudaMemsetAsync(out, 0, (size_t)BB * HH * sizeof(float));
    {
        dim3 grid(BB, 8);
        readout_kernel<<<grid, 256>>>(out);
    }
}

// round 5
// speedup vs baseline: 1.0375x; 1.0375x over previous
#include <cuda_runtime.h>
#include <cuda_bf16.h>
#include <cstdint>

// Problem constants
#define BB   32
#define MAXN 1024
#define FF   215
#define HH   256
#define TT   8
#define LL   3
#define NN   (BB * MAXN)        // 32768
#define EE   524288
#define H3   (3 * HH)           // 768
#define KS   2080               // s row stride: 2048 msg + 8 cnt + 24 pad (mult of 32)

// ---------------------------------------------------------------------------
// Scratch (static __device__ globals — allocation-free per harness rules)
// ---------------------------------------------------------------------------
__device__ __align__(128) float g_h [ (size_t)NN * HH ];
__device__ __align__(128) float g_s [ (size_t)NN * KS ];   // 273 MB
__device__ __align__(128) float g_m [ (size_t)NN * HH ];
__device__ __align__(128) float g_gi[ (size_t)NN * H3 ];
__device__ __align__(128) float g_gh[ (size_t)NN * H3 ];
__device__ __align__(128) float g_Wb[ (size_t)LL * HH * KS ];
// bf16 hi/lo split weights
__device__ __align__(128) __nv_bfloat16 g_Wbh [ (size_t)LL * HH * KS ];
__device__ __align__(128) __nv_bfloat16 g_Wbl [ (size_t)LL * HH * KS ];
__device__ __align__(128) __nv_bfloat16 g_Wph [ 256 * 256 ];
__device__ __align__(128) __nv_bfloat16 g_Wpl [ 256 * 256 ];
__device__ __align__(128) __nv_bfloat16 g_Wihh[ (size_t)LL * H3 * HH ];
__device__ __align__(128) __nv_bfloat16 g_Wihl[ (size_t)LL * H3 * HH ];
__device__ __align__(128) __nv_bfloat16 g_Whhh[ (size_t)LL * H3 * HH ];
__device__ __align__(128) __nv_bfloat16 g_Whhl[ (size_t)LL * H3 * HH ];

// ---------------------------------------------------------------------------
// Helpers (base PTX only — no sm_103a-gated features)
// ---------------------------------------------------------------------------
__device__ __forceinline__ uint32_t smem_u32(const void* p) {
    uint32_t a;
    asm("{ .reg .u64 t; cvta.to.shared.u64 t, %1; cvt.u32.u64 %0, t; }" : "=r"(a) : "l"(p));
    return a;
}

__device__ __forceinline__ void ldsm4(uint32_t& r0, uint32_t& r1, uint32_t& r2, uint32_t& r3,
                                      uint32_t addr)
{
    asm volatile("ldmatrix.sync.aligned.m8n8.x4.shared.b16 {%0,%1,%2,%3}, [%4];"
                 : "=r"(r0), "=r"(r1), "=r"(r2), "=r"(r3) : "r"(addr));
}

__device__ __forceinline__ void mma_bf16(float* c, const uint32_t* a, uint32_t b0, uint32_t b1)
{
    asm volatile("mma.sync.aligned.m16n8k16.row.col.f32.bf16.bf16.f32 "
                 "{%0,%1,%2,%3}, {%4,%5,%6,%7}, {%8,%9}, {%0,%1,%2,%3};"
                 : "+f"(c[0]), "+f"(c[1]), "+f"(c[2]), "+f"(c[3])
                 : "r"(a[0]), "r"(a[1]), "r"(a[2]), "r"(a[3]), "r"(b0), "r"(b1));
}

__device__ __forceinline__ void cpasync16(uint32_t dst, const void* src)
{
    asm volatile("cp.async.ca.shared.global [%0], [%1], 16;" :: "r"(dst), "l"(src));
}
#define CP_COMMIT() asm volatile("cp.async.commit_group;" ::: "memory")
#define CP_WAIT0()  asm volatile("cp.async.wait_group 0;" ::: "memory")

// split fp32 pair -> packed bf16x2 hi + bf16x2 lo  (lo = x - bf16(x))
__device__ __forceinline__ void split2(float x0, float x1, uint32_t& h01, uint32_t& l01) {
    asm("cvt.rn.bf16x2.f32 %0, %1, %2;" : "=r"(h01) : "f"(x1), "f"(x0));   // lo-half = x0
    float h0 = __uint_as_float(h01 << 16);
    float h1 = __uint_as_float(h01 & 0xFFFF0000u);
    float l0 = x0 - h0;
    float l1 = x1 - h1;
    asm("cvt.rn.bf16x2.f32 %0, %1, %2;" : "=r"(l01) : "f"(l1), "f"(l0));
}

// ---------------------------------------------------------------------------
// mma_gemm: C[M x Nc] = A[M x K] @ B[Nc x K]^T (+ bias), fp32 via bf16 3-MMA split.
// Block tile 128(M) x 256(N), K-chunk 32, 512 threads (16 warps, 2m x 8n),
// warp tile 64x32, 2-stage smem double buffer, cp.async for B.
// grid = (Nc/256, M/128).
// ---------------------------------------------------------------------------
#define SA 40                     // smem row stride (bf16 elems) -> conflict-free ldmatrix
#define A_MAT  (128 * SA * 2)     // 10240 B per A matrix (hi or lo)
#define B_MAT  (256 * SA * 2)     // 20480 B per B matrix
#define STG_B  (2 * A_MAT + 2 * B_MAT)   // 61440 B per stage
#define GEMM_SMEM (2 * STG_B)     // 122880 B

__global__ void __launch_bounds__(512)
mma_gemm(const float* __restrict__ A, int lda, int Ka, int avec,
         const __nv_bfloat16* __restrict__ Bh, const __nv_bfloat16* __restrict__ Bl, int ldb,
         const float* __restrict__ bias, float* __restrict__ C, int ldc, int nch)
{
    extern __shared__ __align__(16) char dsm[];

    const int tid  = threadIdx.x;
    const int wid  = tid >> 5;
    const int lane = tid & 31;
    const int m0   = blockIdx.y * 128;
    const int n0   = blockIdx.x * 256;
    const int wm0  = (wid >> 3) * 64;   // warp m-origin (2 rows of warps)
    const int wn0  = (wid & 7) * 32;    // warp n-origin (8 cols of warps)

    const uint32_t sbase = smem_u32(dsm);

    float acc[4][4][4];
#pragma unroll
    for (int i = 0; i < 4; i++)
#pragma unroll
        for (int j = 0; j < 4; j++)
#pragma unroll
            for (int f = 0; f < 4; f++) acc[i][j][f] = 0.0f;

    // ldmatrix per-lane geometry
    const int g  = lane >> 3;
    const int ri = lane & 7;
    const int aRow = ri + ((g & 1) ? 8 : 0);
    const int aK   = (g & 2) ? 8 : 0;
    const int bRow = ri + ((g & 2) ? 8 : 0);
    const int bK   = (g & 1) ? 8 : 0;
    const uint32_t aOff = (uint32_t)(((wm0 + aRow) * SA + aK) * 2);
    const uint32_t bOff = (uint32_t)(((wn0 + bRow) * SA + bK) * 2);

    // per-thread load geometry
    const int arow = tid >> 2;            // 0..127
    const int acg  = (tid & 3) * 8;       // 0,8,16,24

    float ar[8];

    // ---- helpers as lambdas
    auto lda_chunk = [&](int k0) {
        const float* ap = A + (size_t)(m0 + arow) * lda + (k0 + acg);
        if (avec) {
            float4 v0 = *(const float4*)ap;
            float4 v1 = *(const float4*)(ap + 4);
            ar[0]=v0.x; ar[1]=v0.y; ar[2]=v0.z; ar[3]=v0.w;
            ar[4]=v1.x; ar[5]=v1.y; ar[6]=v1.z; ar[7]=v1.w;
        } else {
#pragma unroll
            for (int q = 0; q < 8; ++q) {
                int kg = k0 + acg + q;
                ar[q] = (kg < Ka) ? ap[q] : 0.0f;
            }
        }
    };
    auto ldb_chunk = [&](int k0, uint32_t stg) {
        uint32_t dBh = stg + 2 * A_MAT;
        uint32_t dBl = dBh + B_MAT;
#pragma unroll
        for (int i = 0; i < 2; ++i) {
            int idx = tid + i * 512;
            int r  = idx >> 2;
            int c8 = (idx & 3) * 8;
            size_t go = (size_t)(n0 + r) * ldb + k0 + c8;
            uint32_t off = (uint32_t)((r * SA + c8) * 2);
            cpasync16(dBh + off, Bh + go);
            cpasync16(dBl + off, Bl + go);
        }
    };
    auto sta_chunk = [&](uint32_t stg) {
        uint32_t h01,l01,h23,l23,h45,l45,h67,l67;
        split2(ar[0], ar[1], h01, l01);
        split2(ar[2], ar[3], h23, l23);
        split2(ar[4], ar[5], h45, l45);
        split2(ar[6], ar[7], h67, l67);
        uint32_t off = (uint32_t)((arow * SA + acg) * 2);
        asm volatile("st.shared.v4.b32 [%0], {%1,%2,%3,%4};"
                     :: "r"(stg + off), "r"(h01), "r"(h23), "r"(h45), "r"(h67) : "memory");
        asm volatile("st.shared.v4.b32 [%0], {%1,%2,%3,%4};"
                     :: "r"(stg + A_MAT + off), "r"(l01), "r"(l23), "r"(l45), "r"(l67) : "memory");
    };

    // ---- prologue: fill stage 0
    lda_chunk(0);
    ldb_chunk(0, sbase);
    CP_COMMIT();
    sta_chunk(sbase);
    CP_WAIT0();
    __syncthreads();

    uint32_t p = 0;
    for (int c = 0; c < nch; ++c) {
        const uint32_t stg  = sbase + p * STG_B;
        const uint32_t stgN = sbase + (p ^ 1) * STG_B;

        if (c + 1 < nch) {
            lda_chunk((c + 1) * 32);
            ldb_chunk((c + 1) * 32, stgN);
            CP_COMMIT();
        }

        const uint32_t bAh = stg;
        const uint32_t bAl = stg + A_MAT;
        const uint32_t bBh = stg + 2 * A_MAT;
        const uint32_t bBl = bBh + B_MAT;

#pragma unroll
        for (int kh = 0; kh < 32; kh += 16) {
            uint32_t Af[4][4], Bf[2][4];
#pragma unroll
            for (int i = 0; i < 4; ++i)
                ldsm4(Af[i][0], Af[i][1], Af[i][2], Af[i][3],
                      bAh + aOff + (uint32_t)((i * 16 * SA + kh) * 2));
#pragma unroll
            for (int j = 0; j < 2; ++j)
                ldsm4(Bf[j][0], Bf[j][1], Bf[j][2], Bf[j][3],
                      bBl + bOff + (uint32_t)((j * 16 * SA + kh) * 2));
            // Ah * Bl
#pragma unroll
            for (int i = 0; i < 4; ++i)
#pragma unroll
                for (int jj = 0; jj < 4; ++jj)
                    mma_bf16(acc[i][jj], Af[i], Bf[jj>>1][(jj&1)*2], Bf[jj>>1][(jj&1)*2+1]);
#pragma unroll
            for (int j = 0; j < 2; ++j)
                ldsm4(Bf[j][0], Bf[j][1], Bf[j][2], Bf[j][3],
                      bBh + bOff + (uint32_t)((j * 16 * SA + kh) * 2));
            // Ah * Bh
#pragma unroll
            for (int i = 0; i < 4; ++i)
#pragma unroll
                for (int jj = 0; jj < 4; ++jj)
                    mma_bf16(acc[i][jj], Af[i], Bf[jj>>1][(jj&1)*2], Bf[jj>>1][(jj&1)*2+1]);
#pragma unroll
            for (int i = 0; i < 4; ++i)
                ldsm4(Af[i][0], Af[i][1], Af[i][2], Af[i][3],
                      bAl + aOff + (uint32_t)((i * 16 * SA + kh) * 2));
            // Al * Bh
#pragma unroll
            for (int i = 0; i < 4; ++i)
#pragma unroll
                for (int jj = 0; jj < 4; ++jj)
                    mma_bf16(acc[i][jj], Af[i], Bf[jj>>1][(jj&1)*2], Bf[jj>>1][(jj&1)*2+1]);
        }

        if (c + 1 < nch) {
            sta_chunk(stgN);
            CP_WAIT0();
        }
        __syncthreads();
        p ^= 1;
    }

    // ---- epilogue: direct gmem store with optional bias
    const int qr = lane >> 2;
    const int qc = (lane & 3) * 2;
#pragma unroll
    for (int i = 0; i < 4; ++i) {
        int row = m0 + wm0 + i * 16 + qr;
#pragma unroll
        for (int jj = 0; jj < 4; ++jj) {
            int col = n0 + wn0 + jj * 8 + qc;
            float b0 = 0.0f, b1 = 0.0f;
            if (bias) { b0 = bias[col]; b1 = bias[col + 1]; }
            float2 v0 = make_float2(acc[i][jj][0] + b0, acc[i][jj][1] + b1);
            float2 v1 = make_float2(acc[i][jj][2] + b0, acc[i][jj][3] + b1);
            *(float2*)(C + (size_t)row * ldc + col)       = v0;
            *(float2*)(C + (size_t)(row + 8) * ldc + col) = v1;
        }
    }
}

// ---------------------------------------------------------------------------
// Weight prep
// ---------------------------------------------------------------------------
__global__ void prep_wb_kernel(const float* __restrict__ Wm, const float* __restrict__ bm)
{
    int idx = blockIdx.x * blockDim.x + threadIdx.x;
    if (idx >= LL * HH * KS) return;
    int l   = idx / (HH * KS);
    int rem = idx % (HH * KS);
    int e   = rem / KS;
    int k   = rem % KS;
    float v = 0.0f;
    if (k < TT * HH) {
        int t = k >> 8, d = k & 255;
        v = Wm[((((size_t)l * TT + t) * HH) + e) * HH + d];
    } else if (k < TT * HH + TT) {
        int t = k - TT * HH;
        v = bm[((size_t)l * TT + t) * HH + e];
    }
    g_Wb[idx] = v;
}

__global__ void prep_split(const float* __restrict__ src,
                           __nv_bfloat16* __restrict__ hi, __nv_bfloat16* __restrict__ lo,
                           int rows, int K, int Kb)
{
    int idx = blockIdx.x * blockDim.x + threadIdx.x;
    if (idx >= rows * Kb) return;
    int r = idx / Kb, k = idx - r * Kb;
    float x = (k < K) ? src[(size_t)r * K + k] : 0.0f;
    __nv_bfloat16 hb = __float2bfloat16(x);
    hi[idx] = hb;
    lo[idx] = __float2bfloat16(x - __bfloat162float(hb));
}

// ---------------------------------------------------------------------------
// Scatter: one warp per edge. s[dst, type] += h[src]; cnt[dst, type] += 1
// ---------------------------------------------------------------------------
__device__ __forceinline__ void red_add_v4(float* p, float4 v)
{
    asm volatile("red.global.add.v4.f32 [%0], {%1, %2, %3, %4};"
                 :: "l"(p), "f"(v.x), "f"(v.y), "f"(v.z), "f"(v.w) : "memory");
}

__global__ void scatter_kernel(const int* __restrict__ edge_index,
                               const int* __restrict__ edge_type)
{
    int gw   = (blockIdx.x * blockDim.x + threadIdx.x) >> 5;
    int lane = threadIdx.x & 31;
    if (gw >= EE) return;
    int src = edge_index[gw];
    int dst = edge_index[EE + gw];
    int t   = edge_type[gw];

    const float4* hp = (const float4*)(g_h + (size_t)src * HH);
    float* sp = g_s + (size_t)dst * KS + t * HH;

    float4 v0 = hp[lane];
    float4 v1 = hp[lane + 32];
    red_add_v4(sp + lane * 4, v0);
    red_add_v4(sp + 128 + lane * 4, v1);
    if (lane == 0)
        atomicAdd(g_s + (size_t)dst * KS + TT * HH + t, 1.0f);
}

// ---------------------------------------------------------------------------
// GRU gate elementwise (float4 vectorized)
// ---------------------------------------------------------------------------
__device__ __forceinline__ float sigmoidf_(float x) { return 1.0f / (1.0f + expf(-x)); }
__device__ __forceinline__ float gru1(float ir, float iz, float in_, float hr, float hz, float hn, float hv)
{
    float r  = sigmoidf_(ir + hr);
    float z  = sigmoidf_(iz + hz);
    float ng = tanhf(in_ + r * hn);
    return (1.0f - z) * ng + z * hv;
}

__global__ void gru_kernel()
{
    int idx = blockIdx.x * blockDim.x + threadIdx.x;   // over NN*64
    int n = idx >> 6;
    int j = (idx & 63) * 4;
    const float* gi = g_gi + (size_t)n * H3;
    const float* gh = g_gh + (size_t)n * H3;
    float4 ir = *(const float4*)(gi + j);
    float4 iz = *(const float4*)(gi + 256 + j);
    float4 in_= *(const float4*)(gi + 512 + j);
    float4 hr = *(const float4*)(gh + j);
    float4 hz = *(const float4*)(gh + 256 + j);
    float4 hn = *(const float4*)(gh + 512 + j);
    float*  hp = g_h + (size_t)n * HH + j;
    float4 hv = *(float4*)hp;
    float4 o;
    o.x = gru1(ir.x, iz.x, in_.x, hr.x, hz.x, hn.x, hv.x);
    o.y = gru1(ir.y, iz.y, in_.y, hr.y, hz.y, hn.y, hv.y);
    o.z = gru1(ir.z, iz.z, in_.z, hr.z, hz.z, hn.z, hv.z);
    o.w = gru1(ir.w, iz.w, in_.w, hr.w, hz.w, hn.w, hv.w);
    *(float4*)hp = o;
}

// ---------------------------------------------------------------------------
// Readout
// ---------------------------------------------------------------------------
__global__ void readout_kernel(float* __restrict__ out)
{
    int b = blockIdx.x;
    int c = blockIdx.y;
    int j = threadIdx.x;
    const float* hp = g_h + ((size_t)b * MAXN + (size_t)c * 128) * HH + j;
    float sum = 0.0f;
#pragma unroll 8
    for (int n = 0; n < 128; n++) sum += hp[(size_t)n * HH];
    atomicAdd(&out[b * HH + j], sum);
}

// ---------------------------------------------------------------------------
// Launch
// ---------------------------------------------------------------------------
extern "C" void kernel_launch(void* const* d_in, const int* in_sizes, int n_in,
                              void* d_out, int out_size)
{
    const float* node_features = (const float*)d_in[0];
    const int*   edge_index    = (const int*)  d_in[1];
    const int*   edge_type     = (const int*)  d_in[2];
    const float* Wp  = (const float*)d_in[3];
    const float* bp  = (const float*)d_in[4];
    const float* Wm  = (const float*)d_in[5];
    const float* bm  = (const float*)d_in[6];
    const float* Wih = (const float*)d_in[7];
    const float* Whh = (const float*)d_in[8];
    const float* bih = (const float*)d_in[9];
    const float* bhh = (const float*)d_in[10];
    float* out = (float*)d_out;

    float *p_h, *p_s, *p_m, *p_gi, *p_gh, *p_Wb;
    __nv_bfloat16 *p_Wbh, *p_Wbl, *p_Wph, *p_Wpl, *p_Wihh, *p_Wihl, *p_Whhh, *p_Whhl;
    cudaGetSymbolAddress((void**)&p_h,   g_h);
    cudaGetSymbolAddress((void**)&p_s,   g_s);
    cudaGetSymbolAddress((void**)&p_m,   g_m);
    cudaGetSymbolAddress((void**)&p_gi,  g_gi);
    cudaGetSymbolAddress((void**)&p_gh,  g_gh);
    cudaGetSymbolAddress((void**)&p_Wb,  g_Wb);
    cudaGetSymbolAddress((void**)&p_Wbh, g_Wbh);
    cudaGetSymbolAddress((void**)&p_Wbl, g_Wbl);
    cudaGetSymbolAddress((void**)&p_Wph, g_Wph);
    cudaGetSymbolAddress((void**)&p_Wpl, g_Wpl);
    cudaGetSymbolAddress((void**)&p_Wihh, g_Wihh);
    cudaGetSymbolAddress((void**)&p_Wihl, g_Wihl);
    cudaGetSymbolAddress((void**)&p_Whhh, g_Whhh);
    cudaGetSymbolAddress((void**)&p_Whhl, g_Whhl);

    cudaFuncSetAttribute(mma_gemm, cudaFuncAttributeMaxDynamicSharedMemorySize, GEMM_SMEM);

    // 0) weight prep: fold + split
    {
        int total = LL * HH * KS;
        prep_wb_kernel<<<(total + 255) / 256, 256>>>(Wm, bm);
        prep_split<<<(total + 255) / 256, 256>>>(p_Wb, p_Wbh, p_Wbl, LL * HH, KS, KS);
        int tp = 256 * 256;
        prep_split<<<(tp + 255) / 256, 256>>>(Wp, p_Wph, p_Wpl, HH, FF, 256);
        int tg = LL * H3 * HH;
        prep_split<<<(tg + 255) / 256, 256>>>(Wih, p_Wihh, p_Wihl, LL * H3, HH, HH);
        prep_split<<<(tg + 255) / 256, 256>>>(Whh, p_Whhh, p_Whhl, LL * H3, HH, HH);
    }

    // 1) input projection: h = X @ Wp^T + bp  (K=215 -> 7 chunks of 32, guarded)
    {
        dim3 grid(HH / 256, NN / 128);
        mma_gemm<<<grid, 512, GEMM_SMEM>>>(node_features, FF, FF, 0,
                                           p_Wph, p_Wpl, 256, bp, p_h, HH, 7);
    }

    // 2) layers
    for (int l = 0; l < LL; l++) {
        cudaMemsetAsync(p_s, 0, (size_t)NN * KS * sizeof(float));

        scatter_kernel<<<(EE * 32) / 256, 256>>>(edge_index, edge_type);

        // m = s @ Wb[l]^T  (K = 2080 folds type-linears + cnt*bm bias)
        {
            dim3 grid(HH / 256, NN / 128);
            mma_gemm<<<grid, 512, GEMM_SMEM>>>(p_s, KS, KS, 1,
                                               p_Wbh + (size_t)l * HH * KS,
                                               p_Wbl + (size_t)l * HH * KS, KS,
                                               (const float*)0, p_m, HH, KS / 32);
        }
        // gi = m @ Wih[l]^T + bih[l]
        {
            dim3 grid(H3 / 256, NN / 128);
            mma_gemm<<<grid, 512, GEMM_SMEM>>>(p_m, HH, HH, 1,
                                               p_Wihh + (size_t)l * H3 * HH,
                                               p_Wihl + (size_t)l * H3 * HH, HH,
                                               bih + (size_t)l * H3, p_gi, H3, 8);
        }
        // gh = h @ Whh[l]^T + bhh[l]
        {
            dim3 grid(H3 / 256, NN / 128);
            mma_gemm<<<grid, 512, GEMM_SMEM>>>(p_h, HH, HH, 1,
                                               p_Whhh + (size_t)l * H3 * HH,
                                               p_Whhl + (size_t)l * H3 * HH, HH,
                                               bhh + (size_t)l * H3, p_gh, H3, 8);
        }
        gru_kernel<<<(NN * 64) / 256, 256>>>();
    }

    // 3) readout
    cudaMemsetAsync(out, 0, (size_t)BB * HH * sizeof(float));
    {
        dim3 grid(BB, 8);
        readout_kernel<<<grid, 256>>>(out);
    }
}

// round 6
// speedup vs baseline: 1.1922x; 1.1491x over previous
#include <cuda_runtime.h>
#include <cuda_bf16.h>
#include <cstdint>

// Problem constants
#define BB   32
#define MAXN 1024
#define FF   215
#define HH   256
#define TT   8
#define LL   3
#define NN   (BB * MAXN)        // 32768
#define EE   524288
#define H3   (3 * HH)           // 768
#define TH   (TT * HH)          // 2048

// ---------------------------------------------------------------------------
// Scratch (static __device__ globals — allocation-free per harness rules)
// ---------------------------------------------------------------------------
__device__ __align__(128) float g_h [ (size_t)NN * HH ];   // 33.5 MB
__device__ __align__(128) float g_Ht[ (size_t)NN * TH ];   // 268 MB  transformed per-type messages
__device__ __align__(128) float g_m [ (size_t)NN * HH ];   // 33.5 MB aggregated (L2-resident atomics)
__device__ __align__(128) float g_gi[ (size_t)NN * H3 ];
__device__ __align__(128) float g_gh[ (size_t)NN * H3 ];
// bf16 hi/lo split weights
__device__ __align__(128) __nv_bfloat16 g_Wmh [ (size_t)LL * TH * HH ];
__device__ __align__(128) __nv_bfloat16 g_Wml [ (size_t)LL * TH * HH ];
__device__ __align__(128) __nv_bfloat16 g_Wph [ 256 * 256 ];
__device__ __align__(128) __nv_bfloat16 g_Wpl [ 256 * 256 ];
__device__ __align__(128) __nv_bfloat16 g_Wihh[ (size_t)LL * H3 * HH ];
__device__ __align__(128) __nv_bfloat16 g_Wihl[ (size_t)LL * H3 * HH ];
__device__ __align__(128) __nv_bfloat16 g_Whhh[ (size_t)LL * H3 * HH ];
__device__ __align__(128) __nv_bfloat16 g_Whhl[ (size_t)LL * H3 * HH ];

// ---------------------------------------------------------------------------
// Helpers (base PTX only — no sm_103a-gated features)
// ---------------------------------------------------------------------------
__device__ __forceinline__ uint32_t smem_u32(const void* p) {
    uint32_t a;
    asm("{ .reg .u64 t; cvta.to.shared.u64 t, %1; cvt.u32.u64 %0, t; }" : "=r"(a) : "l"(p));
    return a;
}

__device__ __forceinline__ void ldsm4(uint32_t& r0, uint32_t& r1, uint32_t& r2, uint32_t& r3,
                                      uint32_t addr)
{
    asm volatile("ldmatrix.sync.aligned.m8n8.x4.shared.b16 {%0,%1,%2,%3}, [%4];"
                 : "=r"(r0), "=r"(r1), "=r"(r2), "=r"(r3) : "r"(addr));
}

__device__ __forceinline__ void mma_bf16(float* c, const uint32_t* a, uint32_t b0, uint32_t b1)
{
    asm volatile("mma.sync.aligned.m16n8k16.row.col.f32.bf16.bf16.f32 "
                 "{%0,%1,%2,%3}, {%4,%5,%6,%7}, {%8,%9}, {%0,%1,%2,%3};"
                 : "+f"(c[0]), "+f"(c[1]), "+f"(c[2]), "+f"(c[3])
                 : "r"(a[0]), "r"(a[1]), "r"(a[2]), "r"(a[3]), "r"(b0), "r"(b1));
}

__device__ __forceinline__ void cpasync16(uint32_t dst, const void* src)
{
    asm volatile("cp.async.ca.shared.global [%0], [%1], 16;" :: "r"(dst), "l"(src));
}
#define CP_COMMIT() asm volatile("cp.async.commit_group;" ::: "memory")
#define CP_WAIT0()  asm volatile("cp.async.wait_group 0;" ::: "memory")

// split fp32 pair -> packed bf16x2 hi + bf16x2 lo  (lo = x - bf16(x))
__device__ __forceinline__ void split2(float x0, float x1, uint32_t& h01, uint32_t& l01) {
    asm("cvt.rn.bf16x2.f32 %0, %1, %2;" : "=r"(h01) : "f"(x1), "f"(x0));   // lo-half = x0
    float h0 = __uint_as_float(h01 << 16);
    float h1 = __uint_as_float(h01 & 0xFFFF0000u);
    float l0 = x0 - h0;
    float l1 = x1 - h1;
    asm("cvt.rn.bf16x2.f32 %0, %1, %2;" : "=r"(l01) : "f"(l1), "f"(l0));
}

// ---------------------------------------------------------------------------
// mma_gemm: C[M x Nc] = A[M x K] @ B[Nc x K]^T (+ bias), fp32 via bf16 3-MMA split.
// Block tile 128(M) x 256(N), K-chunk 32, 512 threads (16 warps, 2m x 8n),
// warp tile 64x32, 2-stage smem double buffer, cp.async for B.
// grid = (Nc/256, M/128).
// ---------------------------------------------------------------------------
#define SA 40                     // smem row stride (bf16 elems) -> conflict-free ldmatrix
#define A_MAT  (128 * SA * 2)     // 10240 B per A matrix (hi or lo)
#define B_MAT  (256 * SA * 2)     // 20480 B per B matrix
#define STG_B  (2 * A_MAT + 2 * B_MAT)   // 61440 B per stage
#define GEMM_SMEM (2 * STG_B)     // 122880 B

__global__ void __launch_bounds__(512)
mma_gemm(const float* __restrict__ A, int lda, int Ka, int avec,
         const __nv_bfloat16* __restrict__ Bh, const __nv_bfloat16* __restrict__ Bl, int ldb,
         const float* __restrict__ bias, float* __restrict__ C, int ldc, int nch)
{
    extern __shared__ __align__(16) char dsm[];

    const int tid  = threadIdx.x;
    const int wid  = tid >> 5;
    const int lane = tid & 31;
    const int m0   = blockIdx.y * 128;
    const int n0   = blockIdx.x * 256;
    const int wm0  = (wid >> 3) * 64;   // warp m-origin (2 rows of warps)
    const int wn0  = (wid & 7) * 32;    // warp n-origin (8 cols of warps)

    const uint32_t sbase = smem_u32(dsm);

    float acc[4][4][4];
#pragma unroll
    for (int i = 0; i < 4; i++)
#pragma unroll
        for (int j = 0; j < 4; j++)
#pragma unroll
            for (int f = 0; f < 4; f++) acc[i][j][f] = 0.0f;

    // ldmatrix per-lane geometry
    const int g  = lane >> 3;
    const int ri = lane & 7;
    const int aRow = ri + ((g & 1) ? 8 : 0);
    const int aK   = (g & 2) ? 8 : 0;
    const int bRow = ri + ((g & 2) ? 8 : 0);
    const int bK   = (g & 1) ? 8 : 0;
    const uint32_t aOff = (uint32_t)(((wm0 + aRow) * SA + aK) * 2);
    const uint32_t bOff = (uint32_t)(((wn0 + bRow) * SA + bK) * 2);

    // per-thread load geometry
    const int arow = tid >> 2;            // 0..127
    const int acg  = (tid & 3) * 8;       // 0,8,16,24

    float ar[8];

    auto lda_chunk = [&](int k0) {
        const float* ap = A + (size_t)(m0 + arow) * lda + (k0 + acg);
        if (avec) {
            float4 v0 = *(const float4*)ap;
            float4 v1 = *(const float4*)(ap + 4);
            ar[0]=v0.x; ar[1]=v0.y; ar[2]=v0.z; ar[3]=v0.w;
            ar[4]=v1.x; ar[5]=v1.y; ar[6]=v1.z; ar[7]=v1.w;
        } else {
#pragma unroll
            for (int q = 0; q < 8; ++q) {
                int kg = k0 + acg + q;
                ar[q] = (kg < Ka) ? ap[q] : 0.0f;
            }
        }
    };
    auto ldb_chunk = [&](int k0, uint32_t stg) {
        uint32_t dBh = stg + 2 * A_MAT;
        uint32_t dBl = dBh + B_MAT;
#pragma unroll
        for (int i = 0; i < 2; ++i) {
            int idx = tid + i * 512;
            int r  = idx >> 2;
            int c8 = (idx & 3) * 8;
            size_t go = (size_t)(n0 + r) * ldb + k0 + c8;
            uint32_t off = (uint32_t)((r * SA + c8) * 2);
            cpasync16(dBh + off, Bh + go);
            cpasync16(dBl + off, Bl + go);
        }
    };
    auto sta_chunk = [&](uint32_t stg) {
        uint32_t h01,l01,h23,l23,h45,l45,h67,l67;
        split2(ar[0], ar[1], h01, l01);
        split2(ar[2], ar[3], h23, l23);
        split2(ar[4], ar[5], h45, l45);
        split2(ar[6], ar[7], h67, l67);
        uint32_t off = (uint32_t)((arow * SA + acg) * 2);
        asm volatile("st.shared.v4.b32 [%0], {%1,%2,%3,%4};"
                     :: "r"(stg + off), "r"(h01), "r"(h23), "r"(h45), "r"(h67) : "memory");
        asm volatile("st.shared.v4.b32 [%0], {%1,%2,%3,%4};"
                     :: "r"(stg + A_MAT + off), "r"(l01), "r"(l23), "r"(l45), "r"(l67) : "memory");
    };

    // ---- prologue: fill stage 0
    lda_chunk(0);
    ldb_chunk(0, sbase);
    CP_COMMIT();
    sta_chunk(sbase);
    CP_WAIT0();
    __syncthreads();

    uint32_t p = 0;
    for (int c = 0; c < nch; ++c) {
        const uint32_t stg  = sbase + p * STG_B;
        const uint32_t stgN = sbase + (p ^ 1) * STG_B;

        if (c + 1 < nch) {
            lda_chunk((c + 1) * 32);
            ldb_chunk((c + 1) * 32, stgN);
            CP_COMMIT();
        }

        const uint32_t bAh = stg;
        const uint32_t bAl = stg + A_MAT;
        const uint32_t bBh = stg + 2 * A_MAT;
        const uint32_t bBl = bBh + B_MAT;

#pragma unroll
        for (int kh = 0; kh < 32; kh += 16) {
            uint32_t Af[4][4], Bf[2][4];
#pragma unroll
            for (int i = 0; i < 4; ++i)
                ldsm4(Af[i][0], Af[i][1], Af[i][2], Af[i][3],
                      bAh + aOff + (uint32_t)((i * 16 * SA + kh) * 2));
#pragma unroll
            for (int j = 0; j < 2; ++j)
                ldsm4(Bf[j][0], Bf[j][1], Bf[j][2], Bf[j][3],
                      bBl + bOff + (uint32_t)((j * 16 * SA + kh) * 2));
            // Ah * Bl
#pragma unroll
            for (int i = 0; i < 4; ++i)
#pragma unroll
                for (int jj = 0; jj < 4; ++jj)
                    mma_bf16(acc[i][jj], Af[i], Bf[jj>>1][(jj&1)*2], Bf[jj>>1][(jj&1)*2+1]);
#pragma unroll
            for (int j = 0; j < 2; ++j)
                ldsm4(Bf[j][0], Bf[j][1], Bf[j][2], Bf[j][3],
                      bBh + bOff + (uint32_t)((j * 16 * SA + kh) * 2));
            // Ah * Bh
#pragma unroll
            for (int i = 0; i < 4; ++i)
#pragma unroll
                for (int jj = 0; jj < 4; ++jj)
                    mma_bf16(acc[i][jj], Af[i], Bf[jj>>1][(jj&1)*2], Bf[jj>>1][(jj&1)*2+1]);
#pragma unroll
            for (int i = 0; i < 4; ++i)
                ldsm4(Af[i][0], Af[i][1], Af[i][2], Af[i][3],
                      bAl + aOff + (uint32_t)((i * 16 * SA + kh) * 2));
            // Al * Bh
#pragma unroll
            for (int i = 0; i < 4; ++i)
#pragma unroll
                for (int jj = 0; jj < 4; ++jj)
                    mma_bf16(acc[i][jj], Af[i], Bf[jj>>1][(jj&1)*2], Bf[jj>>1][(jj&1)*2+1]);
        }

        if (c + 1 < nch) {
            sta_chunk(stgN);
            CP_WAIT0();
        }
        __syncthreads();
        p ^= 1;
    }

    // ---- epilogue: direct gmem store with optional bias
    const int qr = lane >> 2;
    const int qc = (lane & 3) * 2;
#pragma unroll
    for (int i = 0; i < 4; ++i) {
        int row = m0 + wm0 + i * 16 + qr;
#pragma unroll
        for (int jj = 0; jj < 4; ++jj) {
            int col = n0 + wn0 + jj * 8 + qc;
            float b0 = 0.0f, b1 = 0.0f;
            if (bias) { b0 = bias[col]; b1 = bias[col + 1]; }
            float2 v0 = make_float2(acc[i][jj][0] + b0, acc[i][jj][1] + b1);
            float2 v1 = make_float2(acc[i][jj][2] + b0, acc[i][jj][3] + b1);
            *(float2*)(C + (size_t)row * ldc + col)       = v0;
            *(float2*)(C + (size_t)(row + 8) * ldc + col) = v1;
        }
    }
}

// ---------------------------------------------------------------------------
// Weight prep: generic fp32 -> bf16 hi/lo split (with K padding)
// ---------------------------------------------------------------------------
__global__ void prep_split(const float* __restrict__ src,
                           __nv_bfloat16* __restrict__ hi, __nv_bfloat16* __restrict__ lo,
                           int rows, int K, int Kb)
{
    int idx = blockIdx.x * blockDim.x + threadIdx.x;
    if (idx >= rows * Kb) return;
    int r = idx / Kb, k = idx - r * Kb;
    float x = (k < K) ? src[(size_t)r * K + k] : 0.0f;
    __nv_bfloat16 hb = __float2bfloat16(x);
    hi[idx] = hb;
    lo[idx] = __float2bfloat16(x - __bfloat162float(hb));
}

// ---------------------------------------------------------------------------
// Scatter: one warp per edge. m[dst] += Ht[src, t]   (m is 33 MB -> L2-resident
// atomics; Ht gather uses streaming loads so it doesn't evict m from L2)
// ---------------------------------------------------------------------------
__device__ __forceinline__ void red_add_v4(float* p, float4 v)
{
    asm volatile("red.global.add.v4.f32 [%0], {%1, %2, %3, %4};"
                 :: "l"(p), "f"(v.x), "f"(v.y), "f"(v.z), "f"(v.w) : "memory");
}

__global__ void scatter_kernel(const int* __restrict__ edge_index,
                               const int* __restrict__ edge_type)
{
    int gw   = (blockIdx.x * blockDim.x + threadIdx.x) >> 5;
    int lane = threadIdx.x & 31;
    if (gw >= EE) return;
    int src = edge_index[gw];
    int dst = edge_index[EE + gw];
    int t   = edge_type[gw];

    const float4* hp = (const float4*)(g_Ht + (size_t)src * TH + t * HH);
    float* mp = g_m + (size_t)dst * HH;

    float4 v0 = __ldcs(hp + lane);
    float4 v1 = __ldcs(hp + lane + 32);
    red_add_v4(mp + lane * 4, v0);
    red_add_v4(mp + 128 + lane * 4, v1);
}

// ---------------------------------------------------------------------------
// GRU gate elementwise (float4 vectorized)
// ---------------------------------------------------------------------------
__device__ __forceinline__ float sigmoidf_(float x) { return 1.0f / (1.0f + expf(-x)); }
__device__ __forceinline__ float gru1(float ir, float iz, float in_, float hr, float hz, float hn, float hv)
{
    float r  = sigmoidf_(ir + hr);
    float z  = sigmoidf_(iz + hz);
    float ng = tanhf(in_ + r * hn);
    return (1.0f - z) * ng + z * hv;
}

__global__ void gru_kernel()
{
    int idx = blockIdx.x * blockDim.x + threadIdx.x;   // over NN*64
    int n = idx >> 6;
    int j = (idx & 63) * 4;
    const float* gi = g_gi + (size_t)n * H3;
    const float* gh = g_gh + (size_t)n * H3;
    float4 ir = *(const float4*)(gi + j);
    float4 iz = *(const float4*)(gi + 256 + j);
    float4 in_= *(const float4*)(gi + 512 + j);
    float4 hr = *(const float4*)(gh + j);
    float4 hz = *(const float4*)(gh + 256 + j);
    float4 hn = *(const float4*)(gh + 512 + j);
    float*  hp = g_h + (size_t)n * HH + j;
    float4 hv = *(float4*)hp;
    float4 o;
    o.x = gru1(ir.x, iz.x, in_.x, hr.x, hz.x, hn.x, hv.x);
    o.y = gru1(ir.y, iz.y, in_.y, hr.y, hz.y, hn.y, hv.y);
    o.z = gru1(ir.z, iz.z, in_.z, hr.z, hz.z, hn.z, hv.z);
    o.w = gru1(ir.w, iz.w, in_.w, hr.w, hz.w, hn.w, hv.w);
    *(float4*)hp = o;
}

// ---------------------------------------------------------------------------
// Readout
// ---------------------------------------------------------------------------
__global__ void readout_kernel(float* __restrict__ out)
{
    int b = blockIdx.x;
    int c = blockIdx.y;
    int j = threadIdx.x;
    const float* hp = g_h + ((size_t)b * MAXN + (size_t)c * 128) * HH + j;
    float sum = 0.0f;
#pragma unroll 8
    for (int n = 0; n < 128; n++) sum += hp[(size_t)n * HH];
    atomicAdd(&out[b * HH + j], sum);
}

// ---------------------------------------------------------------------------
// Launch
// ---------------------------------------------------------------------------
extern "C" void kernel_launch(void* const* d_in, const int* in_sizes, int n_in,
                              void* d_out, int out_size)
{
    const float* node_features = (const float*)d_in[0];
    const int*   edge_index    = (const int*)  d_in[1];
    const int*   edge_type     = (const int*)  d_in[2];
    const float* Wp  = (const float*)d_in[3];
    const float* bp  = (const float*)d_in[4];
    const float* Wm  = (const float*)d_in[5];   // (L, T, H, H) == (L, 2048, 256)
    const float* bm  = (const float*)d_in[6];   // (L, T, H)   == (L, 2048)
    const float* Wih = (const float*)d_in[7];
    const float* Whh = (const float*)d_in[8];
    const float* bih = (const float*)d_in[9];
    const float* bhh = (const float*)d_in[10];
    float* out = (float*)d_out;

    float *p_h, *p_Ht, *p_m, *p_gi, *p_gh;
    __nv_bfloat16 *p_Wmh, *p_Wml, *p_Wph, *p_Wpl, *p_Wihh, *p_Wihl, *p_Whhh, *p_Whhl;
    cudaGetSymbolAddress((void**)&p_h,   g_h);
    cudaGetSymbolAddress((void**)&p_Ht,  g_Ht);
    cudaGetSymbolAddress((void**)&p_m,   g_m);
    cudaGetSymbolAddress((void**)&p_gi,  g_gi);
    cudaGetSymbolAddress((void**)&p_gh,  g_gh);
    cudaGetSymbolAddress((void**)&p_Wmh, g_Wmh);
    cudaGetSymbolAddress((void**)&p_Wml, g_Wml);
    cudaGetSymbolAddress((void**)&p_Wph, g_Wph);
    cudaGetSymbolAddress((void**)&p_Wpl, g_Wpl);
    cudaGetSymbolAddress((void**)&p_Wihh, g_Wihh);
    cudaGetSymbolAddress((void**)&p_Wihl, g_Wihl);
    cudaGetSymbolAddress((void**)&p_Whhh, g_Whhh);
    cudaGetSymbolAddress((void**)&p_Whhl, g_Whhl);

    cudaFuncSetAttribute(mma_gemm, cudaFuncAttributeMaxDynamicSharedMemorySize, GEMM_SMEM);

    // 0) weight prep: split (Wm needs no fold — (T*H, H) rows are exactly what we need)
    {
        int tm = LL * TH * HH;
        prep_split<<<(tm + 255) / 256, 256>>>(Wm, p_Wmh, p_Wml, LL * TH, HH, HH);
        int tp = 256 * 256;
        prep_split<<<(tp + 255) / 256, 256>>>(Wp, p_Wph, p_Wpl, HH, FF, 256);
        int tg = LL * H3 * HH;
        prep_split<<<(tg + 255) / 256, 256>>>(Wih, p_Wihh, p_Wihl, LL * H3, HH, HH);
        prep_split<<<(tg + 255) / 256, 256>>>(Whh, p_Whhh, p_Whhl, LL * H3, HH, HH);
    }

    // 1) input projection: h = X @ Wp^T + bp  (K=215 -> 7 chunks of 32, guarded)
    {
        dim3 grid(HH / 256, NN / 128);
        mma_gemm<<<grid, 512, GEMM_SMEM>>>(node_features, FF, FF, 0,
                                           p_Wph, p_Wpl, 256, bp, p_h, HH, 7);
    }

    // 2) layers
    for (int l = 0; l < LL; l++) {
        // 2a) Ht = h @ Wm[l]^T + bm[l]   (N x 2048; bias subsumes per-edge bm add)
        {
            dim3 grid(TH / 256, NN / 128);
            mma_gemm<<<grid, 512, GEMM_SMEM>>>(p_h, HH, HH, 1,
                                               p_Wmh + (size_t)l * TH * HH,
                                               p_Wml + (size_t)l * TH * HH, HH,
                                               bm + (size_t)l * TH, p_Ht, TH, 8);
        }

        // 2b) m = 0; m[dst] += Ht[src, t]  (L2-resident atomics)
        cudaMemsetAsync(p_m, 0, (size_t)NN * HH * sizeof(float));
        scatter_kernel<<<(EE * 32) / 256, 256>>>(edge_index, edge_type);

        // 2c) gi = m @ Wih[l]^T + bih[l]
        {
            dim3 grid(H3 / 256, NN / 128);
            mma_gemm<<<grid, 512, GEMM_SMEM>>>(p_m, HH, HH, 1,
                                               p_Wihh + (size_t)l * H3 * HH,
                                               p_Wihl + (size_t)l * H3 * HH, HH,
                                               bih + (size_t)l * H3, p_gi, H3, 8);
        }
        // 2d) gh = h @ Whh[l]^T + bhh[l]
        {
            dim3 grid(H3 / 256, NN / 128);
            mma_gemm<<<grid, 512, GEMM_SMEM>>>(p_h, HH, HH, 1,
                                               p_Whhh + (size_t)l * H3 * HH,
                                               p_Whhl + (size_t)l * H3 * HH, HH,
                                               bhh + (size_t)l * H3, p_gh, H3, 8);
        }
        // 2e) GRU gates (updates h in place)
        gru_kernel<<<(NN * 64) / 256, 256>>>();
    }

    // 3) readout
    cudaMemsetAsync(out, 0, (size_t)BB * HH * sizeof(float));
    {
        dim3 grid(BB, 8);
        readout_kernel<<<grid, 256>>>(out);
    }
}

// round 9
// speedup vs baseline: 1.1973x; 1.0043x over previous
#include <cuda_runtime.h>
#include <cuda_bf16.h>
#include <cstdint>

// Problem constants
#define BB   32
#define MAXN 1024
#define FF   215
#define HH   256
#define TT   8
#define LL   3
#define NN   (BB * MAXN)        // 32768
#define EE   524288
#define H3   (3 * HH)           // 768
#define TH   (TT * HH)          // 2048

// ---------------------------------------------------------------------------
// Scratch (static __device__ globals — allocation-free per harness rules)
// ---------------------------------------------------------------------------
__device__ __align__(128) float g_h [ (size_t)NN * HH ];   // 33.5 MB
__device__ __align__(128) float g_Ht[ (size_t)NN * TH ];   // 268 MB  transformed per-type messages
__device__ __align__(128) float g_m [ (size_t)NN * HH ];   // 33.5 MB aggregated (L2-resident atomics)
__device__ __align__(128) float g_gi[ (size_t)NN * H3 ];
__device__ __align__(128) float g_gh[ (size_t)NN * H3 ];
// bf16 hi/lo split weights
__device__ __align__(128) __nv_bfloat16 g_Wmh [ (size_t)LL * TH * HH ];
__device__ __align__(128) __nv_bfloat16 g_Wml [ (size_t)LL * TH * HH ];
__device__ __align__(128) __nv_bfloat16 g_Wph [ 256 * 256 ];
__device__ __align__(128) __nv_bfloat16 g_Wpl [ 256 * 256 ];
__device__ __align__(128) __nv_bfloat16 g_Wihh[ (size_t)LL * H3 * HH ];
__device__ __align__(128) __nv_bfloat16 g_Wihl[ (size_t)LL * H3 * HH ];
__device__ __align__(128) __nv_bfloat16 g_Whhh[ (size_t)LL * H3 * HH ];
__device__ __align__(128) __nv_bfloat16 g_Whhl[ (size_t)LL * H3 * HH ];

// ---------------------------------------------------------------------------
// Helpers (base PTX only — no sm_103a-gated features)
// ---------------------------------------------------------------------------
__device__ __forceinline__ uint32_t smem_u32(const void* p) {
    uint32_t a;
    asm("{ .reg .u64 t; cvta.to.shared.u64 t, %1; cvt.u32.u64 %0, t; }" : "=r"(a) : "l"(p));
    return a;
}

__device__ __forceinline__ void ldsm4(uint32_t& r0, uint32_t& r1, uint32_t& r2, uint32_t& r3,
                                      uint32_t addr)
{
    asm volatile("ldmatrix.sync.aligned.m8n8.x4.shared.b16 {%0,%1,%2,%3}, [%4];"
                 : "=r"(r0), "=r"(r1), "=r"(r2), "=r"(r3) : "r"(addr));
}

__device__ __forceinline__ void mma_bf16(float* c, const uint32_t* a, uint32_t b0, uint32_t b1)
{
    asm volatile("mma.sync.aligned.m16n8k16.row.col.f32.bf16.bf16.f32 "
                 "{%0,%1,%2,%3}, {%4,%5,%6,%7}, {%8,%9}, {%0,%1,%2,%3};"
                 : "+f"(c[0]), "+f"(c[1]), "+f"(c[2]), "+f"(c[3])
                 : "r"(a[0]), "r"(a[1]), "r"(a[2]), "r"(a[3]), "r"(b0), "r"(b1));
}

__device__ __forceinline__ void cpasync16(uint32_t dst, const void* src)
{
    asm volatile("cp.async.ca.shared.global [%0], [%1], 16;" :: "r"(dst), "l"(src));
}
#define CP_COMMIT() asm volatile("cp.async.commit_group;" ::: "memory")
#define CP_WAIT0()  asm volatile("cp.async.wait_group 0;" ::: "memory")

// split fp32 pair -> packed bf16x2 hi + bf16x2 lo  (lo = x - bf16(x))
__device__ __forceinline__ void split2(float x0, float x1, uint32_t& h01, uint32_t& l01) {
    asm("cvt.rn.bf16x2.f32 %0, %1, %2;" : "=r"(h01) : "f"(x1), "f"(x0));   // lo-half = x0
    float h0 = __uint_as_float(h01 << 16);
    float h1 = __uint_as_float(h01 & 0xFFFF0000u);
    float l0 = x0 - h0;
    float l1 = x1 - h1;
    asm("cvt.rn.bf16x2.f32 %0, %1, %2;" : "=r"(l01) : "f"(l1), "f"(l0));
}

__device__ __forceinline__ void red_add_v4(float* p, float4 v)
{
    asm volatile("red.global.add.v4.f32 [%0], {%1, %2, %3, %4};"
                 :: "l"(p), "f"(v.x), "f"(v.y), "f"(v.z), "f"(v.w) : "memory");
}

// ---------------------------------------------------------------------------
// gemm_core: C[M x Nc] = A[M x K] @ B[Nc x K]^T (+ bias), fp32 via bf16 3-MMA split.
// Block tile 128(M) x 256(N), K-chunk 32, 512 threads (16 warps, 2m x 8n),
// warp tile 64x32, 2-stage smem double buffer, cp.async for B.
// ---------------------------------------------------------------------------
#define SA 40                     // smem row stride (bf16 elems) -> conflict-free ldmatrix
#define A_MAT  (128 * SA * 2)     // 10240 B per A matrix (hi or lo)
#define B_MAT  (256 * SA * 2)     // 20480 B per B matrix
#define STG_B  (2 * A_MAT + 2 * B_MAT)   // 61440 B per stage
#define GEMM_SMEM (2 * STG_B)     // 122880 B

__device__ __forceinline__ void
gemm_core(char* dsm, int m0, int n0,
          const float* __restrict__ A, int lda, int Ka, int avec,
          const __nv_bfloat16* __restrict__ Bh, const __nv_bfloat16* __restrict__ Bl, int ldb,
          const float* __restrict__ bias, float* __restrict__ C, int ldc, int nch)
{
    const int tid  = threadIdx.x;
    const int wid  = tid >> 5;
    const int lane = tid & 31;
    const int wm0  = (wid >> 3) * 64;   // warp m-origin (2 rows of warps)
    const int wn0  = (wid & 7) * 32;    // warp n-origin (8 cols of warps)

    const uint32_t sbase = smem_u32(dsm);

    float acc[4][4][4];
#pragma unroll
    for (int i = 0; i < 4; i++)
#pragma unroll
        for (int j = 0; j < 4; j++)
#pragma unroll
            for (int f = 0; f < 4; f++) acc[i][j][f] = 0.0f;

    // ldmatrix per-lane geometry
    const int g  = lane >> 3;
    const int ri = lane & 7;
    const int aRow = ri + ((g & 1) ? 8 : 0);
    const int aK   = (g & 2) ? 8 : 0;
    const int bRow = ri + ((g & 2) ? 8 : 0);
    const int bK   = (g & 1) ? 8 : 0;
    const uint32_t aOff = (uint32_t)(((wm0 + aRow) * SA + aK) * 2);
    const uint32_t bOff = (uint32_t)(((wn0 + bRow) * SA + bK) * 2);

    // per-thread load geometry
    const int arow = tid >> 2;            // 0..127
    const int acg  = (tid & 3) * 8;       // 0,8,16,24

    float ar[8];

    auto lda_chunk = [&](int k0) {
        const float* ap = A + (size_t)(m0 + arow) * lda + (k0 + acg);
        if (avec) {
            float4 v0 = *(const float4*)ap;
            float4 v1 = *(const float4*)(ap + 4);
            ar[0]=v0.x; ar[1]=v0.y; ar[2]=v0.z; ar[3]=v0.w;
            ar[4]=v1.x; ar[5]=v1.y; ar[6]=v1.z; ar[7]=v1.w;
        } else {
#pragma unroll
            for (int q = 0; q < 8; ++q) {
                int kg = k0 + acg + q;
                ar[q] = (kg < Ka) ? ap[q] : 0.0f;
            }
        }
    };
    auto ldb_chunk = [&](int k0, uint32_t stg) {
        uint32_t dBh = stg + 2 * A_MAT;
        uint32_t dBl = dBh + B_MAT;
#pragma unroll
        for (int i = 0; i < 2; ++i) {
            int idx = tid + i * 512;
            int r  = idx >> 2;
            int c8 = (idx & 3) * 8;
            size_t go = (size_t)(n0 + r) * ldb + k0 + c8;
            uint32_t off = (uint32_t)((r * SA + c8) * 2);
            cpasync16(dBh + off, Bh + go);
            cpasync16(dBl + off, Bl + go);
        }
    };
    auto sta_chunk = [&](uint32_t stg) {
        uint32_t h01,l01,h23,l23,h45,l45,h67,l67;
        split2(ar[0], ar[1], h01, l01);
        split2(ar[2], ar[3], h23, l23);
        split2(ar[4], ar[5], h45, l45);
        split2(ar[6], ar[7], h67, l67);
        uint32_t off = (uint32_t)((arow * SA + acg) * 2);
        asm volatile("st.shared.v4.b32 [%0], {%1,%2,%3,%4};"
                     :: "r"(stg + off), "r"(h01), "r"(h23), "r"(h45), "r"(h67) : "memory");
        asm volatile("st.shared.v4.b32 [%0], {%1,%2,%3,%4};"
                     :: "r"(stg + A_MAT + off), "r"(l01), "r"(l23), "r"(l45), "r"(l67) : "memory");
    };

    // ---- prologue: fill stage 0
    lda_chunk(0);
    ldb_chunk(0, sbase);
    CP_COMMIT();
    sta_chunk(sbase);
    CP_WAIT0();
    __syncthreads();

    uint32_t p = 0;
    for (int c = 0; c < nch; ++c) {
        const uint32_t stg  = sbase + p * STG_B;
        const uint32_t stgN = sbase + (p ^ 1) * STG_B;

        if (c + 1 < nch) {
            lda_chunk((c + 1) * 32);
            ldb_chunk((c + 1) * 32, stgN);
            CP_COMMIT();
        }

        const uint32_t bAh = stg;
        const uint32_t bAl = stg + A_MAT;
        const uint32_t bBh = stg + 2 * A_MAT;
        const uint32_t bBl = bBh + B_MAT;

#pragma unroll
        for (int kh = 0; kh < 32; kh += 16) {
            uint32_t Af[4][4], Bf[2][4];
#pragma unroll
            for (int i = 0; i < 4; ++i)
                ldsm4(Af[i][0], Af[i][1], Af[i][2], Af[i][3],
                      bAh + aOff + (uint32_t)((i * 16 * SA + kh) * 2));
#pragma unroll
            for (int j = 0; j < 2; ++j)
                ldsm4(Bf[j][0], Bf[j][1], Bf[j][2], Bf[j][3],
                      bBl + bOff + (uint32_t)((j * 16 * SA + kh) * 2));
            // Ah * Bl
#pragma unroll
            for (int i = 0; i < 4; ++i)
#pragma unroll
                for (int jj = 0; jj < 4; ++jj)
                    mma_bf16(acc[i][jj], Af[i], Bf[jj>>1][(jj&1)*2], Bf[jj>>1][(jj&1)*2+1]);
#pragma unroll
            for (int j = 0; j < 2; ++j)
                ldsm4(Bf[j][0], Bf[j][1], Bf[j][2], Bf[j][3],
                      bBh + bOff + (uint32_t)((j * 16 * SA + kh) * 2));
            // Ah * Bh
#pragma unroll
            for (int i = 0; i < 4; ++i)
#pragma unroll
                for (int jj = 0; jj < 4; ++jj)
                    mma_bf16(acc[i][jj], Af[i], Bf[jj>>1][(jj&1)*2], Bf[jj>>1][(jj&1)*2+1]);
#pragma unroll
            for (int i = 0; i < 4; ++i)
                ldsm4(Af[i][0], Af[i][1], Af[i][2], Af[i][3],
                      bAl + aOff + (uint32_t)((i * 16 * SA + kh) * 2));
            // Al * Bh
#pragma unroll
            for (int i = 0; i < 4; ++i)
#pragma unroll
                for (int jj = 0; jj < 4; ++jj)
                    mma_bf16(acc[i][jj], Af[i], Bf[jj>>1][(jj&1)*2], Bf[jj>>1][(jj&1)*2+1]);
        }

        if (c + 1 < nch) {
            sta_chunk(stgN);
            CP_WAIT0();
        }
        __syncthreads();
        p ^= 1;
    }

    // ---- epilogue: direct gmem store with optional bias
    const int qr = lane >> 2;
    const int qc = (lane & 3) * 2;
#pragma unroll
    for (int i = 0; i < 4; ++i) {
        int row = m0 + wm0 + i * 16 + qr;
#pragma unroll
        for (int jj = 0; jj < 4; ++jj) {
            int col = n0 + wn0 + jj * 8 + qc;
            float b0 = 0.0f, b1 = 0.0f;
            if (bias) { b0 = bias[col]; b1 = bias[col + 1]; }
            float2 v0 = make_float2(acc[i][jj][0] + b0, acc[i][jj][1] + b1);
            float2 v1 = make_float2(acc[i][jj][2] + b0, acc[i][jj][3] + b1);
            *(float2*)(C + (size_t)row * ldc + col)       = v0;
            *(float2*)(C + (size_t)(row + 8) * ldc + col) = v1;
        }
    }
}

// plain GEMM launch wrapper: grid = (Nc/256, M/128)
__global__ void __launch_bounds__(512)
mma_gemm(const float* __restrict__ A, int lda, int Ka, int avec,
         const __nv_bfloat16* __restrict__ Bh, const __nv_bfloat16* __restrict__ Bl, int ldb,
         const float* __restrict__ bias, float* __restrict__ C, int ldc, int nch)
{
    extern __shared__ __align__(16) char dsm[];
    gemm_core(dsm, blockIdx.y * 128, blockIdx.x * 256,
              A, lda, Ka, avec, Bh, Bl, ldb, bias, C, ldc, nch);
}

// ---------------------------------------------------------------------------
// Fused gh-GEMM + scatter (grid union): blocks [0, GH_BLOCKS) compute
// gh = h @ Whh^T + bhh; blocks [GH_BLOCKS, +SCAT_BLOCKS) run the edge scatter
// m[dst] += Ht[src, t]. Tensor-bound and memory-bound blocks co-schedule.
// ---------------------------------------------------------------------------
#define GHX (H3 / 256)                 // 3
#define GH_BLOCKS (GHX * (NN / 128))   // 768
#define EDGES_PER_BLK 512              // 16 warps x 32 edges
#define SCAT_BLOCKS (EE / EDGES_PER_BLK)  // 1024

__global__ void __launch_bounds__(512)
gh_scatter_kernel(const float* __restrict__ A,
                  const __nv_bfloat16* __restrict__ Bh, const __nv_bfloat16* __restrict__ Bl,
                  const float* __restrict__ bias, float* __restrict__ C,
                  const int* __restrict__ edge_index, const int* __restrict__ edge_type)
{
    extern __shared__ __align__(16) char dsm[];
    if (blockIdx.x < GH_BLOCKS) {
        int bx = blockIdx.x % GHX;
        int by = blockIdx.x / GHX;
        gemm_core(dsm, by * 128, bx * 256, A, HH, HH, 1, Bh, Bl, HH, bias, C, H3, 8);
    } else {
        const int blk  = blockIdx.x - GH_BLOCKS;
        const int wid  = threadIdx.x >> 5;
        const int lane = threadIdx.x & 31;
        const int e0   = blk * EDGES_PER_BLK + wid * 32;

        // coalesced index load, one per lane; broadcast via shfl per iteration
        const int se = edge_index[e0 + lane];
        const int de = edge_index[EE + e0 + lane];
        const int te = edge_type[e0 + lane];

#pragma unroll 4
        for (int i = 0; i < 32; ++i) {
            int src = __shfl_sync(0xffffffffu, se, i);
            int dst = __shfl_sync(0xffffffffu, de, i);
            int t   = __shfl_sync(0xffffffffu, te, i);
            const float4* hp = (const float4*)(g_Ht + (size_t)src * TH + t * HH);
            float* mp = g_m + (size_t)dst * HH;
            float4 v0 = __ldcs(hp + lane);
            float4 v1 = __ldcs(hp + lane + 32);
            red_add_v4(mp + lane * 4, v0);
            red_add_v4(mp + 128 + lane * 4, v1);
        }
    }
}

// ---------------------------------------------------------------------------
// Weight prep: generic fp32 -> bf16 hi/lo split (with K padding)
// ---------------------------------------------------------------------------
__global__ void prep_split(const float* __restrict__ src,
                           __nv_bfloat16* __restrict__ hi, __nv_bfloat16* __restrict__ lo,
                           int rows, int K, int Kb)
{
    int idx = blockIdx.x * blockDim.x + threadIdx.x;
    if (idx >= rows * Kb) return;
    int r = idx / Kb, k = idx - r * Kb;
    float x = (k < K) ? src[(size_t)r * K + k] : 0.0f;
    __nv_bfloat16 hb = __float2bfloat16(x);
    hi[idx] = hb;
    lo[idx] = __float2bfloat16(x - __bfloat162float(hb));
}

// ---------------------------------------------------------------------------
// GRU gate elementwise (float4 vectorized)
// ---------------------------------------------------------------------------
__device__ __forceinline__ float sigmoidf_(float x) { return 1.0f / (1.0f + expf(-x)); }
__device__ __forceinline__ float gru1(float ir, float iz, float in_, float hr, float hz, float hn, float hv)
{
    float r  = sigmoidf_(ir + hr);
    float z  = sigmoidf_(iz + hz);
    float ng = tanhf(in_ + r * hn);
    return (1.0f - z) * ng + z * hv;
}

__global__ void gru_kernel()
{
    int idx = blockIdx.x * blockDim.x + threadIdx.x;   // over NN*64
    int n = idx >> 6;
    int j = (idx & 63) * 4;
    const float* gi = g_gi + (size_t)n * H3;
    const float* gh = g_gh + (size_t)n * H3;
    float4 ir = *(const float4*)(gi + j);
    float4 iz = *(const float4*)(gi + 256 + j);
    float4 in_= *(const float4*)(gi + 512 + j);
    float4 hr = *(const float4*)(gh + j);
    float4 hz = *(const float4*)(gh + 256 + j);
    float4 hn = *(const float4*)(gh + 512 + j);
    float*  hp = g_h + (size_t)n * HH + j;
    float4 hv = *(float4*)hp;
    float4 o;
    o.x = gru1(ir.x, iz.x, in_.x, hr.x, hz.x, hn.x, hv.x);
    o.y = gru1(ir.y, iz.y, in_.y, hr.y, hz.y, hn.y, hv.y);
    o.z = gru1(ir.z, iz.z, in_.z, hr.z, hz.z, hn.z, hv.z);
    o.w = gru1(ir.w, iz.w, in_.w, hr.w, hz.w, hn.w, hv.w);
    *(float4*)hp = o;
}

// ---------------------------------------------------------------------------
// Readout
// ---------------------------------------------------------------------------
__global__ void readout_kernel(float* __restrict__ out)
{
    int b = blockIdx.x;
    int c = blockIdx.y;
    int j = threadIdx.x;
    const float* hp = g_h + ((size_t)b * MAXN + (size_t)c * 128) * HH + j;
    float sum = 0.0f;
#pragma unroll 8
    for (int n = 0; n < 128; n++) sum += hp[(size_t)n * HH];
    atomicAdd(&out[b * HH + j], sum);
}

// ---------------------------------------------------------------------------
// Launch
// ---------------------------------------------------------------------------
extern "C" void kernel_launch(void* const* d_in, const int* in_sizes, int n_in,
                              void* d_out, int out_size)
{
    const float* node_features = (const float*)d_in[0];
    const int*   edge_index    = (const int*)  d_in[1];
    const int*   edge_type     = (const int*)  d_in[2];
    const float* Wp  = (const float*)d_in[3];
    const float* bp  = (const float*)d_in[4];
    const float* Wm  = (const float*)d_in[5];   // (L, T, H, H) == (L, 2048, 256)
    const float* bm  = (const float*)d_in[6];   // (L, T, H)   == (L, 2048)
    const float* Wih = (const float*)d_in[7];
    const float* Whh = (const float*)d_in[8];
    const float* bih = (const float*)d_in[9];
    const float* bhh = (const float*)d_in[10];
    float* out = (float*)d_out;

    float *p_h, *p_Ht, *p_m, *p_gi, *p_gh;
    __nv_bfloat16 *p_Wmh, *p_Wml, *p_Wph, *p_Wpl, *p_Wihh, *p_Wihl, *p_Whhh, *p_Whhl;
    cudaGetSymbolAddress((void**)&p_h,   g_h);
    cudaGetSymbolAddress((void**)&p_Ht,  g_Ht);
    cudaGetSymbolAddress((void**)&p_m,   g_m);
    cudaGetSymbolAddress((void**)&p_gi,  g_gi);
    cudaGetSymbolAddress((void**)&p_gh,  g_gh);
    cudaGetSymbolAddress((void**)&p_Wmh, g_Wmh);
    cudaGetSymbolAddress((void**)&p_Wml, g_Wml);
    cudaGetSymbolAddress((void**)&p_Wph, g_Wph);
    cudaGetSymbolAddress((void**)&p_Wpl, g_Wpl);
    cudaGetSymbolAddress((void**)&p_Wihh, g_Wihh);
    cudaGetSymbolAddress((void**)&p_Wihl, g_Wihl);
    cudaGetSymbolAddress((void**)&p_Whhh, g_Whhh);
    cudaGetSymbolAddress((void**)&p_Whhl, g_Whhl);

    cudaFuncSetAttribute(mma_gemm, cudaFuncAttributeMaxDynamicSharedMemorySize, GEMM_SMEM);
    cudaFuncSetAttribute(gh_scatter_kernel, cudaFuncAttributeMaxDynamicSharedMemorySize, GEMM_SMEM);

    // 0) weight prep: split (Wm needs no fold — (T*H, H) rows are exactly what we need)
    {
        int tm = LL * TH * HH;
        prep_split<<<(tm + 255) / 256, 256>>>(Wm, p_Wmh, p_Wml, LL * TH, HH, HH);
        int tp = 256 * 256;
        prep_split<<<(tp + 255) / 256, 256>>>(Wp, p_Wph, p_Wpl, HH, FF, 256);
        int tg = LL * H3 * HH;
        prep_split<<<(tg + 255) / 256, 256>>>(Wih, p_Wihh, p_Wihl, LL * H3, HH, HH);
        prep_split<<<(tg + 255) / 256, 256>>>(Whh, p_Whhh, p_Whhl, LL * H3, HH, HH);
    }

    // 1) input projection: h = X @ Wp^T + bp  (K=215 -> 7 chunks of 32, guarded)
    {
        dim3 grid(HH / 256, NN / 128);
        mma_gemm<<<grid, 512, GEMM_SMEM>>>(node_features, FF, FF, 0,
                                           p_Wph, p_Wpl, 256, bp, p_h, HH, 7);
    }

    // 2) layers
    for (int l = 0; l < LL; l++) {
        // 2a) zero m (off the Ht->scatter critical path)
        cudaMemsetAsync(p_m, 0, (size_t)NN * HH * sizeof(float));

        // 2b) Ht = h @ Wm[l]^T + bm[l]   (N x 2048; bias subsumes per-edge bm add)
        {
            dim3 grid(TH / 256, NN / 128);
            mma_gemm<<<grid, 512, GEMM_SMEM>>>(p_h, HH, HH, 1,
                                               p_Wmh + (size_t)l * TH * HH,
                                               p_Wml + (size_t)l * TH * HH, HH,
                                               bm + (size_t)l * TH, p_Ht, TH, 8);
        }

        // 2c) FUSED: gh = h @ Whh[l]^T + bhh[l]  ||  m[dst] += Ht[src, t]
        {
            dim3 grid(GH_BLOCKS + SCAT_BLOCKS);
            gh_scatter_kernel<<<grid, 512, GEMM_SMEM>>>(p_h,
                                                        p_Whhh + (size_t)l * H3 * HH,
                                                        p_Whhl + (size_t)l * H3 * HH,
                                                        bhh + (size_t)l * H3, p_gh,
                                                        edge_index, edge_type);
        }

        // 2d) gi = m @ Wih[l]^T + bih[l]
        {
            dim3 grid(H3 / 256, NN / 128);
            mma_gemm<<<grid, 512, GEMM_SMEM>>>(p_m, HH, HH, 1,
                                               p_Wihh + (size_t)l * H3 * HH,
                                               p_Wihl + (size_t)l * H3 * HH, HH,
                                               bih + (size_t)l * H3, p_gi, H3, 8);
        }
        // 2e) GRU gates (updates h in place)
        gru_kernel<<<(NN * 64) / 256, 256>>>();
    }

    // 3) readout
    cudaMemsetAsync(out, 0, (size_t)BB * HH * sizeof(float));
    {
        dim3 grid(BB, 8);
        readout_kernel<<<grid, 256>>>(out);
    }
}

// round 12
// speedup vs baseline: 1.2546x; 1.0478x over previous
#include <cuda_runtime.h>
#include <cuda_bf16.h>
#include <cstdint>

// Problem constants
#define BB   32
#define MAXN 1024
#define FF   215
#define HH   256
#define TT   8
#define LL   3
#define NN   (BB * MAXN)        // 32768
#define EE   524288
#define H3   (3 * HH)           // 768
#define TH   (TT * HH)          // 2048
#define NBKT 2048               // (NN/128) * TT

// ---------------------------------------------------------------------------
// Scratch (static __device__ globals — allocation-free per harness rules)
// ---------------------------------------------------------------------------
__device__ __align__(128) float g_h [ (size_t)NN * HH ];   // 33.5 MB
__device__ __align__(128) float g_m [ (size_t)NN * HH ];   // 33.5 MB aggregated (L2-resident atomics)
__device__ __align__(128) float g_gi[ (size_t)NN * H3 ];
__device__ __align__(128) float g_gh[ (size_t)NN * H3 ];
// edge bucketing by (src_block, type)
__device__ int g_bkt_cnt[NBKT];
__device__ int g_bkt_cur[NBKT];
__device__ int g_bkt_off[NBKT + 1];
__device__ int g_edge_sorted[EE];     // packed: dst<<7 | src_local
// bf16 hi/lo split weights
__device__ __align__(128) __nv_bfloat16 g_Wmh [ (size_t)LL * TH * HH ];
__device__ __align__(128) __nv_bfloat16 g_Wml [ (size_t)LL * TH * HH ];
__device__ __align__(128) __nv_bfloat16 g_Wph [ 256 * 256 ];
__device__ __align__(128) __nv_bfloat16 g_Wpl [ 256 * 256 ];
__device__ __align__(128) __nv_bfloat16 g_Wihh[ (size_t)LL * H3 * HH ];
__device__ __align__(128) __nv_bfloat16 g_Wihl[ (size_t)LL * H3 * HH ];
__device__ __align__(128) __nv_bfloat16 g_Whhh[ (size_t)LL * H3 * HH ];
__device__ __align__(128) __nv_bfloat16 g_Whhl[ (size_t)LL * H3 * HH ];

// ---------------------------------------------------------------------------
// Helpers (base PTX only)
// ---------------------------------------------------------------------------
__device__ __forceinline__ uint32_t smem_u32(const void* p) {
    uint32_t a;
    asm("{ .reg .u64 t; cvta.to.shared.u64 t, %1; cvt.u32.u64 %0, t; }" : "=r"(a) : "l"(p));
    return a;
}

__device__ __forceinline__ void ldsm4(uint32_t& r0, uint32_t& r1, uint32_t& r2, uint32_t& r3,
                                      uint32_t addr)
{
    asm volatile("ldmatrix.sync.aligned.m8n8.x4.shared.b16 {%0,%1,%2,%3}, [%4];"
                 : "=r"(r0), "=r"(r1), "=r"(r2), "=r"(r3) : "r"(addr));
}

__device__ __forceinline__ void mma_bf16(float* c, const uint32_t* a, uint32_t b0, uint32_t b1)
{
    asm volatile("mma.sync.aligned.m16n8k16.row.col.f32.bf16.bf16.f32 "
                 "{%0,%1,%2,%3}, {%4,%5,%6,%7}, {%8,%9}, {%0,%1,%2,%3};"
                 : "+f"(c[0]), "+f"(c[1]), "+f"(c[2]), "+f"(c[3])
                 : "r"(a[0]), "r"(a[1]), "r"(a[2]), "r"(a[3]), "r"(b0), "r"(b1));
}

__device__ __forceinline__ void cpasync16(uint32_t dst, const void* src)
{
    asm volatile("cp.async.ca.shared.global [%0], [%1], 16;" :: "r"(dst), "l"(src));
}
#define CP_COMMIT() asm volatile("cp.async.commit_group;" ::: "memory")
#define CP_WAIT0()  asm volatile("cp.async.wait_group 0;" ::: "memory")

__device__ __forceinline__ void split2(float x0, float x1, uint32_t& h01, uint32_t& l01) {
    asm("cvt.rn.bf16x2.f32 %0, %1, %2;" : "=r"(h01) : "f"(x1), "f"(x0));
    float h0 = __uint_as_float(h01 << 16);
    float h1 = __uint_as_float(h01 & 0xFFFF0000u);
    float l0 = x0 - h0;
    float l1 = x1 - h1;
    asm("cvt.rn.bf16x2.f32 %0, %1, %2;" : "=r"(l01) : "f"(l1), "f"(l0));
}

__device__ __forceinline__ void red_add_v4(float* p, float4 v)
{
    asm volatile("red.global.add.v4.f32 [%0], {%1, %2, %3, %4};"
                 :: "l"(p), "f"(v.x), "f"(v.y), "f"(v.z), "f"(v.w) : "memory");
}

// ---------------------------------------------------------------------------
// gemm_core: C[M x Nc] = A[M x K] @ B[Nc x K]^T (+ bias), fp32 via bf16 3-MMA split.
// Block tile 128(M) x 256(N), K-chunk 32, 512 threads (16 warps, 2m x 8n),
// 2-stage smem double buffer, cp.async for B.
// If smemTile != nullptr, the result tile is stored to smem (row stride TSTR)
// instead of gmem C.
// ---------------------------------------------------------------------------
#define SA 40
#define A_MAT  (128 * SA * 2)
#define B_MAT  (256 * SA * 2)
#define STG_B  (2 * A_MAT + 2 * B_MAT)   // 61440 B per stage
#define GEMM_SMEM (2 * STG_B)            // 122880 B
#define TSTR 264                         // tile row stride in floats (264*4=1056B, 16B-mult)
#define TILE_SMEM (128 * TSTR * 4)       // 135168 B
#define FUSED_SMEM (TILE_SMEM > GEMM_SMEM ? TILE_SMEM : GEMM_SMEM)

__device__ __forceinline__ void
gemm_core(char* dsm, int m0, int n0,
          const float* __restrict__ A, int lda, int Ka, int avec,
          const __nv_bfloat16* __restrict__ Bh, const __nv_bfloat16* __restrict__ Bl, int ldb,
          const float* __restrict__ bias, float* __restrict__ C, int ldc, int nch,
          float* smemTile)
{
    const int tid  = threadIdx.x;
    const int wid  = tid >> 5;
    const int lane = tid & 31;
    const int wm0  = (wid >> 3) * 64;
    const int wn0  = (wid & 7) * 32;

    const uint32_t sbase = smem_u32(dsm);

    float acc[4][4][4];
#pragma unroll
    for (int i = 0; i < 4; i++)
#pragma unroll
        for (int j = 0; j < 4; j++)
#pragma unroll
            for (int f = 0; f < 4; f++) acc[i][j][f] = 0.0f;

    const int g  = lane >> 3;
    const int ri = lane & 7;
    const int aRow = ri + ((g & 1) ? 8 : 0);
    const int aK   = (g & 2) ? 8 : 0;
    const int bRow = ri + ((g & 2) ? 8 : 0);
    const int bK   = (g & 1) ? 8 : 0;
    const uint32_t aOff = (uint32_t)(((wm0 + aRow) * SA + aK) * 2);
    const uint32_t bOff = (uint32_t)(((wn0 + bRow) * SA + bK) * 2);

    const int arow = tid >> 2;
    const int acg  = (tid & 3) * 8;

    float ar[8];

    auto lda_chunk = [&](int k0) {
        const float* ap = A + (size_t)(m0 + arow) * lda + (k0 + acg);
        if (avec) {
            float4 v0 = *(const float4*)ap;
            float4 v1 = *(const float4*)(ap + 4);
            ar[0]=v0.x; ar[1]=v0.y; ar[2]=v0.z; ar[3]=v0.w;
            ar[4]=v1.x; ar[5]=v1.y; ar[6]=v1.z; ar[7]=v1.w;
        } else {
#pragma unroll
            for (int q = 0; q < 8; ++q) {
                int kg = k0 + acg + q;
                ar[q] = (kg < Ka) ? ap[q] : 0.0f;
            }
        }
    };
    auto ldb_chunk = [&](int k0, uint32_t stg) {
        uint32_t dBh = stg + 2 * A_MAT;
        uint32_t dBl = dBh + B_MAT;
#pragma unroll
        for (int i = 0; i < 2; ++i) {
            int idx = tid + i * 512;
            int r  = idx >> 2;
            int c8 = (idx & 3) * 8;
            size_t go = (size_t)(n0 + r) * ldb + k0 + c8;
            uint32_t off = (uint32_t)((r * SA + c8) * 2);
            cpasync16(dBh + off, Bh + go);
            cpasync16(dBl + off, Bl + go);
        }
    };
    auto sta_chunk = [&](uint32_t stg) {
        uint32_t h01,l01,h23,l23,h45,l45,h67,l67;
        split2(ar[0], ar[1], h01, l01);
        split2(ar[2], ar[3], h23, l23);
        split2(ar[4], ar[5], h45, l45);
        split2(ar[6], ar[7], h67, l67);
        uint32_t off = (uint32_t)((arow * SA + acg) * 2);
        asm volatile("st.shared.v4.b32 [%0], {%1,%2,%3,%4};"
                     :: "r"(stg + off), "r"(h01), "r"(h23), "r"(h45), "r"(h67) : "memory");
        asm volatile("st.shared.v4.b32 [%0], {%1,%2,%3,%4};"
                     :: "r"(stg + A_MAT + off), "r"(l01), "r"(l23), "r"(l45), "r"(l67) : "memory");
    };

    lda_chunk(0);
    ldb_chunk(0, sbase);
    CP_COMMIT();
    sta_chunk(sbase);
    CP_WAIT0();
    __syncthreads();

    uint32_t p = 0;
    for (int c = 0; c < nch; ++c) {
        const uint32_t stg  = sbase + p * STG_B;
        const uint32_t stgN = sbase + (p ^ 1) * STG_B;

        if (c + 1 < nch) {
            lda_chunk((c + 1) * 32);
            ldb_chunk((c + 1) * 32, stgN);
            CP_COMMIT();
        }

        const uint32_t bAh = stg;
        const uint32_t bAl = stg + A_MAT;
        const uint32_t bBh = stg + 2 * A_MAT;
        const uint32_t bBl = bBh + B_MAT;

#pragma unroll
        for (int kh = 0; kh < 32; kh += 16) {
            uint32_t Af[4][4], Bf[2][4];
#pragma unroll
            for (int i = 0; i < 4; ++i)
                ldsm4(Af[i][0], Af[i][1], Af[i][2], Af[i][3],
                      bAh + aOff + (uint32_t)((i * 16 * SA + kh) * 2));
#pragma unroll
            for (int j = 0; j < 2; ++j)
                ldsm4(Bf[j][0], Bf[j][1], Bf[j][2], Bf[j][3],
                      bBl + bOff + (uint32_t)((j * 16 * SA + kh) * 2));
#pragma unroll
            for (int i = 0; i < 4; ++i)
#pragma unroll
                for (int jj = 0; jj < 4; ++jj)
                    mma_bf16(acc[i][jj], Af[i], Bf[jj>>1][(jj&1)*2], Bf[jj>>1][(jj&1)*2+1]);
#pragma unroll
            for (int j = 0; j < 2; ++j)
                ldsm4(Bf[j][0], Bf[j][1], Bf[j][2], Bf[j][3],
                      bBh + bOff + (uint32_t)((j * 16 * SA + kh) * 2));
#pragma unroll
            for (int i = 0; i < 4; ++i)
#pragma unroll
                for (int jj = 0; jj < 4; ++jj)
                    mma_bf16(acc[i][jj], Af[i], Bf[jj>>1][(jj&1)*2], Bf[jj>>1][(jj&1)*2+1]);
#pragma unroll
            for (int i = 0; i < 4; ++i)
                ldsm4(Af[i][0], Af[i][1], Af[i][2], Af[i][3],
                      bAl + aOff + (uint32_t)((i * 16 * SA + kh) * 2));
#pragma unroll
            for (int i = 0; i < 4; ++i)
#pragma unroll
                for (int jj = 0; jj < 4; ++jj)
                    mma_bf16(acc[i][jj], Af[i], Bf[jj>>1][(jj&1)*2], Bf[jj>>1][(jj&1)*2+1]);
        }

        if (c + 1 < nch) {
            sta_chunk(stgN);
            CP_WAIT0();
        }
        __syncthreads();
        p ^= 1;
    }

    // ---- epilogue
    const int qr = lane >> 2;
    const int qc = (lane & 3) * 2;
    if (smemTile) {
        // store to smem tile (overwrites stages; all MMAs retired after final sync)
#pragma unroll
        for (int i = 0; i < 4; ++i) {
            int row = wm0 + i * 16 + qr;
#pragma unroll
            for (int jj = 0; jj < 4; ++jj) {
                int col = wn0 + jj * 8 + qc;
                float b0 = bias[n0 + col], b1 = bias[n0 + col + 1];
                *(float2*)(smemTile + (size_t)row * TSTR + col) =
                    make_float2(acc[i][jj][0] + b0, acc[i][jj][1] + b1);
                *(float2*)(smemTile + (size_t)(row + 8) * TSTR + col) =
                    make_float2(acc[i][jj][2] + b0, acc[i][jj][3] + b1);
            }
        }
    } else {
#pragma unroll
        for (int i = 0; i < 4; ++i) {
            int row = m0 + wm0 + i * 16 + qr;
#pragma unroll
            for (int jj = 0; jj < 4; ++jj) {
                int col = n0 + wn0 + jj * 8 + qc;
                float b0 = 0.0f, b1 = 0.0f;
                if (bias) { b0 = bias[col]; b1 = bias[col + 1]; }
                *(float2*)(C + (size_t)row * ldc + col) =
                    make_float2(acc[i][jj][0] + b0, acc[i][jj][1] + b1);
                *(float2*)(C + (size_t)(row + 8) * ldc + col) =
                    make_float2(acc[i][jj][2] + b0, acc[i][jj][3] + b1);
            }
        }
    }
}

// plain GEMM launch wrapper: grid = (Nc/256, M/128)
__global__ void __launch_bounds__(512)
mma_gemm(const float* __restrict__ A, int lda, int Ka, int avec,
         const __nv_bfloat16* __restrict__ Bh, const __nv_bfloat16* __restrict__ Bl, int ldb,
         const float* __restrict__ bias, float* __restrict__ C, int ldc, int nch)
{
    extern __shared__ __align__(16) char dsm[];
    gemm_core(dsm, blockIdx.y * 128, blockIdx.x * 256,
              A, lda, Ka, avec, Bh, Bl, ldb, bias, C, ldc, nch, nullptr);
}

// ---------------------------------------------------------------------------
// Fused Ht-GEMM + scatter: block b = (node_block nb = b>>3, type t = b&7).
// Computes Ht tile = h[nb*128:+128] @ Wm[l, t*256:+256]^T + bm into SMEM,
// then scatters bucket edges: m[dst] += tile[src_local].
// ---------------------------------------------------------------------------
__global__ void __launch_bounds__(512)
ht_scatter_kernel(const float* __restrict__ A,
                  const __nv_bfloat16* __restrict__ Bh, const __nv_bfloat16* __restrict__ Bl,
                  const float* __restrict__ bias)
{
    extern __shared__ __align__(16) char dsm[];
    float* tile = (float*)dsm;
    const int b  = blockIdx.x;
    const int nb = b >> 3;
    const int t  = b & 7;

    gemm_core(dsm, nb * 128, t * 256, A, HH, HH, 1, Bh, Bl, HH,
              bias, nullptr, 0, 8, tile);
    __syncthreads();

    const int wid  = threadIdx.x >> 5;
    const int lane = threadIdx.x & 31;
    const int e0 = g_bkt_off[b];
    const int e1 = g_bkt_off[b + 1];
    for (int e = e0 + wid; e < e1; e += 16) {
        int pe   = g_edge_sorted[e];
        int srcl = pe & 127;
        int dst  = pe >> 7;
        const float* rp = tile + (size_t)srcl * TSTR;
        float4 v0 = *(const float4*)(rp + lane * 4);
        float4 v1 = *(const float4*)(rp + 128 + lane * 4);
        float* mp = g_m + (size_t)dst * HH;
        red_add_v4(mp + lane * 4, v0);
        red_add_v4(mp + 128 + lane * 4, v1);
    }
}

// ---------------------------------------------------------------------------
// Edge bucketing (once per launch; edge_index constant)
// ---------------------------------------------------------------------------
__global__ void bkt_count_kernel(const int* __restrict__ ei, const int* __restrict__ et)
{
    int e = blockIdx.x * blockDim.x + threadIdx.x;
    if (e >= EE) return;
    int bkt = (ei[e] >> 7) * TT + et[e];
    atomicAdd(&g_bkt_cnt[bkt], 1);
}

__global__ void bkt_scan_kernel()
{
    __shared__ int sa[NBKT], sb[NBKT];
    int tidx = threadIdx.x;   // 1024 threads
    for (int i = tidx; i < NBKT; i += 1024) sa[i] = g_bkt_cnt[i];
    __syncthreads();
    int* a = sa; int* bb = sb;
    for (int off = 1; off < NBKT; off <<= 1) {
        for (int i = tidx; i < NBKT; i += 1024) {
            int v = a[i];
            if (i >= off) v += a[i - off];
            bb[i] = v;
        }
        __syncthreads();
        int* tmp = a; a = bb; bb = tmp;
    }
    for (int i = tidx; i < NBKT; i += 1024) {
        g_bkt_off[i + 1] = a[i];
        g_bkt_cur[i] = 0;
    }
    if (tidx == 0) g_bkt_off[0] = 0;
}

__global__ void bkt_fill_kernel(const int* __restrict__ ei, const int* __restrict__ et)
{
    int e = blockIdx.x * blockDim.x + threadIdx.x;
    if (e >= EE) return;
    int src = ei[e];
    int dst = ei[EE + e];
    int bkt = (src >> 7) * TT + et[e];
    int pos = g_bkt_off[bkt] + atomicAdd(&g_bkt_cur[bkt], 1);
    g_edge_sorted[pos] = (dst << 7) | (src & 127);
}

// ---------------------------------------------------------------------------
// Weight prep: generic fp32 -> bf16 hi/lo split (with K padding)
// ---------------------------------------------------------------------------
__global__ void prep_split(const float* __restrict__ src,
                           __nv_bfloat16* __restrict__ hi, __nv_bfloat16* __restrict__ lo,
                           int rows, int K, int Kb)
{
    int idx = blockIdx.x * blockDim.x + threadIdx.x;
    if (idx >= rows * Kb) return;
    int r = idx / Kb, k = idx - r * Kb;
    float x = (k < K) ? src[(size_t)r * K + k] : 0.0f;
    __nv_bfloat16 hb = __float2bfloat16(x);
    hi[idx] = hb;
    lo[idx] = __float2bfloat16(x - __bfloat162float(hb));
}

// ---------------------------------------------------------------------------
// GRU gate elementwise (float4 vectorized)
// ---------------------------------------------------------------------------
__device__ __forceinline__ float sigmoidf_(float x) { return 1.0f / (1.0f + expf(-x)); }
__device__ __forceinline__ float gru1(float ir, float iz, float in_, float hr, float hz, float hn, float hv)
{
    float r  = sigmoidf_(ir + hr);
    float z  = sigmoidf_(iz + hz);
    float ng = tanhf(in_ + r * hn);
    return (1.0f - z) * ng + z * hv;
}

__global__ void gru_kernel()
{
    int idx = blockIdx.x * blockDim.x + threadIdx.x;   // over NN*64
    int n = idx >> 6;
    int j = (idx & 63) * 4;
    const float* gi = g_gi + (size_t)n * H3;
    const float* gh = g_gh + (size_t)n * H3;
    float4 ir = *(const float4*)(gi + j);
    float4 iz = *(const float4*)(gi + 256 + j);
    float4 in_= *(const float4*)(gi + 512 + j);
    float4 hr = *(const float4*)(gh + j);
    float4 hz = *(const float4*)(gh + 256 + j);
    float4 hn = *(const float4*)(gh + 512 + j);
    float*  hp = g_h + (size_t)n * HH + j;
    float4 hv = *(float4*)hp;
    float4 o;
    o.x = gru1(ir.x, iz.x, in_.x, hr.x, hz.x, hn.x, hv.x);
    o.y = gru1(ir.y, iz.y, in_.y, hr.y, hz.y, hn.y, hv.y);
    o.z = gru1(ir.z, iz.z, in_.z, hr.z, hz.z, hn.z, hv.z);
    o.w = gru1(ir.w, iz.w, in_.w, hr.w, hz.w, hn.w, hv.w);
    *(float4*)hp = o;
}

// ---------------------------------------------------------------------------
// Readout
// ---------------------------------------------------------------------------
__global__ void readout_kernel(float* __restrict__ out)
{
    int b = blockIdx.x;
    int c = blockIdx.y;
    int j = threadIdx.x;
    const float* hp = g_h + ((size_t)b * MAXN + (size_t)c * 128) * HH + j;
    float sum = 0.0f;
#pragma unroll 8
    for (int n = 0; n < 128; n++) sum += hp[(size_t)n * HH];
    atomicAdd(&out[b * HH + j], sum);
}

// ---------------------------------------------------------------------------
// Launch
// ---------------------------------------------------------------------------
extern "C" void kernel_launch(void* const* d_in, const int* in_sizes, int n_in,
                              void* d_out, int out_size)
{
    const float* node_features = (const float*)d_in[0];
    const int*   edge_index    = (const int*)  d_in[1];
    const int*   edge_type     = (const int*)  d_in[2];
    const float* Wp  = (const float*)d_in[3];
    const float* bp  = (const float*)d_in[4];
    const float* Wm  = (const float*)d_in[5];   // (L, T, H, H) == (L, 2048, 256)
    const float* bm  = (const float*)d_in[6];   // (L, 2048)
    const float* Wih = (const float*)d_in[7];
    const float* Whh = (const float*)d_in[8];
    const float* bih = (const float*)d_in[9];
    const float* bhh = (const float*)d_in[10];
    float* out = (float*)d_out;

    float *p_h, *p_m, *p_gi, *p_gh;
    int *p_cnt;
    __nv_bfloat16 *p_Wmh, *p_Wml, *p_Wph, *p_Wpl, *p_Wihh, *p_Wihl, *p_Whhh, *p_Whhl;
    cudaGetSymbolAddress((void**)&p_h,   g_h);
    cudaGetSymbolAddress((void**)&p_m,   g_m);
    cudaGetSymbolAddress((void**)&p_gi,  g_gi);
    cudaGetSymbolAddress((void**)&p_gh,  g_gh);
    cudaGetSymbolAddress((void**)&p_cnt, g_bkt_cnt);
    cudaGetSymbolAddress((void**)&p_Wmh, g_Wmh);
    cudaGetSymbolAddress((void**)&p_Wml, g_Wml);
    cudaGetSymbolAddress((void**)&p_Wph, g_Wph);
    cudaGetSymbolAddress((void**)&p_Wpl, g_Wpl);
    cudaGetSymbolAddress((void**)&p_Wihh, g_Wihh);
    cudaGetSymbolAddress((void**)&p_Wihl, g_Wihl);
    cudaGetSymbolAddress((void**)&p_Whhh, g_Whhh);
    cudaGetSymbolAddress((void**)&p_Whhl, g_Whhl);

    cudaFuncSetAttribute(mma_gemm, cudaFuncAttributeMaxDynamicSharedMemorySize, GEMM_SMEM);
    cudaFuncSetAttribute(ht_scatter_kernel, cudaFuncAttributeMaxDynamicSharedMemorySize, FUSED_SMEM);

    // 0a) edge bucketing (edges constant across layers)
    cudaMemsetAsync(p_cnt, 0, NBKT * sizeof(int));
    bkt_count_kernel<<<EE / 256, 256>>>(edge_index, edge_type);
    bkt_scan_kernel<<<1, 1024>>>();
    bkt_fill_kernel<<<EE / 256, 256>>>(edge_index, edge_type);

    // 0b) weight prep: bf16 hi/lo splits
    {
        int tm = LL * TH * HH;
        prep_split<<<(tm + 255) / 256, 256>>>(Wm, p_Wmh, p_Wml, LL * TH, HH, HH);
        int tp = 256 * 256;
        prep_split<<<(tp + 255) / 256, 256>>>(Wp, p_Wph, p_Wpl, HH, FF, 256);
        int tg = LL * H3 * HH;
        prep_split<<<(tg + 255) / 256, 256>>>(Wih, p_Wihh, p_Wihl, LL * H3, HH, HH);
        prep_split<<<(tg + 255) / 256, 256>>>(Whh, p_Whhh, p_Whhl, LL * H3, HH, HH);
    }

    // 1) input projection: h = X @ Wp^T + bp
    {
        dim3 grid(HH / 256, NN / 128);
        mma_gemm<<<grid, 512, GEMM_SMEM>>>(node_features, FF, FF, 0,
                                           p_Wph, p_Wpl, 256, bp, p_h, HH, 7);
    }

    // 2) layers
    for (int l = 0; l < LL; l++) {
        // 2a) zero m
        cudaMemsetAsync(p_m, 0, (size_t)NN * HH * sizeof(float));

        // 2b) FUSED: Ht tile in smem + scatter m[dst] += Ht[src, t]
        ht_scatter_kernel<<<NBKT, 512, FUSED_SMEM>>>(p_h,
                                                     p_Wmh + (size_t)l * TH * HH,
                                                     p_Wml + (size_t)l * TH * HH,
                                                     bm + (size_t)l * TH);

        // 2c) gh = h @ Whh[l]^T + bhh[l]
        {
            dim3 grid(H3 / 256, NN / 128);
            mma_gemm<<<grid, 512, GEMM_SMEM>>>(p_h, HH, HH, 1,
                                               p_Whhh + (size_t)l * H3 * HH,
                                               p_Whhl + (size_t)l * H3 * HH, HH,
                                               bhh + (size_t)l * H3, p_gh, H3, 8);
        }
        // 2d) gi = m @ Wih[l]^T + bih[l]
        {
            dim3 grid(H3 / 256, NN / 128);
            mma_gemm<<<grid, 512, GEMM_SMEM>>>(p_m, HH, HH, 1,
                                               p_Wihh + (size_t)l * H3 * HH,
                                               p_Wihl + (size_t)l * H3 * HH, HH,
                                               bih + (size_t)l * H3, p_gi, H3, 8);
        }
        // 2e) GRU gates (updates h in place)
        gru_kernel<<<(NN * 64) / 256, 256>>>();
    }

    // 3) readout
    cudaMemsetAsync(out, 0, (size_t)BB * HH * sizeof(float));
    {
        dim3 grid(BB, 8);
        readout_kernel<<<grid, 256>>>(out);
    }
}